// round 11
// baseline (speedup 1.0000x reference)
#include <cuda_runtime.h>
#include <cuda_bf16.h>
#include <cstdint>
#include <cstddef>

#define EPSV 1e-8f
#define CHUNK 64
#define NCHUNK 32
#define NCH 4096  // channels = B*NH*HD

// Gate pre-activations scratch: [B=4][S=2048][4 gates][NH=4][HD=256] fp32 = 128 MiB
static __device__ float g_gates[33554432];
// per-(chunk,channel) local state (F, m_loc, c_loc, n_loc)
static __device__ float4 g_cstate[NCHUNK * NCH];
// per-(chunk,channel) carry-in state (m, c, n, -)
static __device__ float4 g_carry[NCHUNK * NCH];
// Pre-split weights: bf16 hi/lo, layout [gh][n][k] like W
static __device__ __nv_bfloat16 g_W0[1048576];
static __device__ __nv_bfloat16 g_W1[1048576];

// ---------------------------------------------------------------------------
__device__ __forceinline__ uint32_t smem_u32(const void* p) {
    uint32_t a;
    asm("{ .reg .u64 t; cvta.to.shared.u64 t, %1; cvt.u32.u64 %0, t; }" : "=r"(a) : "l"(p));
    return a;
}
__device__ __forceinline__ void ldsm4(uint32_t* r, uint32_t addr) {
    asm volatile("ldmatrix.sync.aligned.m8n8.x4.shared.b16 {%0,%1,%2,%3}, [%4];"
                 : "=r"(r[0]), "=r"(r[1]), "=r"(r[2]), "=r"(r[3]) : "r"(addr));
}
__device__ __forceinline__ void mma16816(float* c, const uint32_t* a, const uint32_t* b) {
    asm volatile(
        "mma.sync.aligned.m16n8k16.row.col.f32.bf16.bf16.f32 "
        "{%0,%1,%2,%3}, {%4,%5,%6,%7}, {%8,%9}, {%0,%1,%2,%3};"
        : "+f"(c[0]), "+f"(c[1]), "+f"(c[2]), "+f"(c[3])
        : "r"(a[0]), "r"(a[1]), "r"(a[2]), "r"(a[3]), "r"(b[0]), "r"(b[1]));
}
#define CP_ASYNC16(sa, gp) \
    asm volatile("cp.async.ca.shared.global [%0], [%1], 16;" :: "r"(sa), "l"(gp))
#define CP_COMMIT() asm volatile("cp.async.commit_group;" ::: "memory")
#define CP_WAIT0()  asm volatile("cp.async.wait_group 0;" ::: "memory")

// convert 8 fp32 -> bf16 hi (uint2 x2) + lo (uint2 x2)
__device__ __forceinline__ void split8(const float4& v0, const float4& v1,
                                       uint2& h_a, uint2& h_b, uint2& l_a, uint2& l_b) {
    __nv_bfloat162 h0 = __floats2bfloat162_rn(v0.x, v0.y);
    __nv_bfloat162 h1 = __floats2bfloat162_rn(v0.z, v0.w);
    __nv_bfloat162 h2 = __floats2bfloat162_rn(v1.x, v1.y);
    __nv_bfloat162 h3 = __floats2bfloat162_rn(v1.z, v1.w);
    __nv_bfloat162 l0 = __floats2bfloat162_rn(v0.x - __bfloat162float(h0.x), v0.y - __bfloat162float(h0.y));
    __nv_bfloat162 l1 = __floats2bfloat162_rn(v0.z - __bfloat162float(h1.x), v0.w - __bfloat162float(h1.y));
    __nv_bfloat162 l2 = __floats2bfloat162_rn(v1.x - __bfloat162float(h2.x), v1.y - __bfloat162float(h2.y));
    __nv_bfloat162 l3 = __floats2bfloat162_rn(v1.z - __bfloat162float(h3.x), v1.w - __bfloat162float(h3.y));
    h_a.x = *(const uint32_t*)&h0; h_a.y = *(const uint32_t*)&h1;
    h_b.x = *(const uint32_t*)&h2; h_b.y = *(const uint32_t*)&h3;
    l_a.x = *(const uint32_t*)&l0; l_a.y = *(const uint32_t*)&l1;
    l_b.x = *(const uint32_t*)&l2; l_b.y = *(const uint32_t*)&l3;
}

// ===========================================================================
// Kernel 0: pre-split W (fp32 -> bf16 hi + bf16 lo). 1,048,576 elements.
// ===========================================================================
__global__ __launch_bounds__(256) void wsplit_kernel(const float* __restrict__ W)
{
    const int i = blockIdx.x * 256 + threadIdx.x;  // float4 id, 262144 total
    float4 v = *(const float4*)(W + (size_t)i * 4);
    __nv_bfloat162 h0 = __floats2bfloat162_rn(v.x, v.y);
    __nv_bfloat162 h1 = __floats2bfloat162_rn(v.z, v.w);
    __nv_bfloat162 l0 = __floats2bfloat162_rn(v.x - __bfloat162float(h0.x), v.y - __bfloat162float(h0.y));
    __nv_bfloat162 l1 = __floats2bfloat162_rn(v.z - __bfloat162float(h1.x), v.w - __bfloat162float(h1.y));
    uint2 ha, la;
    ha.x = *(const uint32_t*)&h0; ha.y = *(const uint32_t*)&h1;
    la.x = *(const uint32_t*)&l0; la.y = *(const uint32_t*)&l1;
    *(uint2*)&g_W0[(size_t)i * 4] = ha;
    *(uint2*)&g_W1[(size_t)i * 4] = la;
}

// ===========================================================================
// Kernel 1: block-diagonal GEMM via mma.sync bf16 (3-term 2-split)
//   grid (64 m-tiles, 64 = 16 gh x 4 n-quarters), 256 threads = 8 warps
//   (4 m x 2 n), warp tile 32x32, block tile 128x64. K=256 in 8 chunks of 32.
//   ~95 regs/thread + 60KB smem -> 2 CTAs/SM: prologue/epilogue/barrier
//   exposure of one CTA hides under the other's MMA phase.
//   A: LDG->convert->STS double-buffered. B: cp.async double-buffered.
//   B0 fragments cached in regs across terms (A1*B0 reuses them).
//   smem rows: 32 bf16 (64B) + 16B pad = 80B pitch (conflict-free ldmatrix).
// ===========================================================================
#define APITCH 80
#define SA0 0            // 128 rows * 80B = 10240
#define SA1 10240
#define SB0 20480        // 64 rows * 80B = 5120
#define SB1 25600
#define BUFSZ 30720
#define SMEM_GEMM (2 * BUFSZ)

__global__ __launch_bounds__(256, 2) void gemm_mma_kernel(
    const float* __restrict__ X, const float* __restrict__ Bias)
{
    extern __shared__ __align__(16) char smem[];
    const uint32_t sb = smem_u32(smem);

    const int tid  = threadIdx.x;
    const int lane = tid & 31;
    const int wid  = tid >> 5;
    const int wm   = (wid & 3) * 32;   // warp m offset (0..96)
    const int wn   = (wid >> 2) * 32;  // warp n offset (0 or 32)
    const int bx   = blockIdx.x;
    const int gh   = blockIdx.y >> 2;
    const int nq   = blockIdx.y & 3;   // n-quarter (64 cols each)

    float c[2][4][4];
#pragma unroll
    for (int i = 0; i < 2; ++i)
#pragma unroll
        for (int j = 0; j < 4; ++j)
#pragma unroll
            for (int q = 0; q < 4; ++q) c[i][j][q] = 0.f;

    // ---- staging assignments (256 threads) ----
    // A: thread -> row (tid>>1) [0..127], 16-float half (tid&1)
    const float* xp = X + (size_t)(bx * 128 + (tid >> 1)) * 4096 + gh * 256 + (tid & 1) * 16;
    const uint32_t aSt = (uint32_t)(tid >> 1) * APITCH + (tid & 1) * 32;
    // B: thread -> row (tid>>2) [0..63 of this n-quarter], 16B seg (tid&3)
    const __nv_bfloat16* w0p = g_W0 + (size_t)gh * 65536 + (size_t)(nq * 64 + (tid >> 2)) * 256
                             + (tid & 3) * 8;
    const __nv_bfloat16* w1p = g_W1 + (size_t)gh * 65536 + (size_t)(nq * 64 + (tid >> 2)) * 256
                             + (tid & 3) * 8;
    const uint32_t bSt = (uint32_t)(tid >> 2) * APITCH + (tid & 3) * 16;

    // ldmatrix base offsets (within a buffer)
    const uint32_t aRowOff = SA0 + (uint32_t)(wm + (lane & 15)) * APITCH + (lane >> 4) * 16;
    const uint32_t bRowOff = SB0 + (uint32_t)(wn + (lane & 7) + (lane >> 4) * 8) * APITCH
                           + ((lane >> 3) & 1) * 16;

    // ---- prologue: stage chunk 0 into buffer 0 ----
    {
        float4 v0 = *(const float4*)xp;
        float4 v1 = *(const float4*)(xp + 4);
        float4 v2 = *(const float4*)(xp + 8);
        float4 v3 = *(const float4*)(xp + 12);
        uint2 ha, hb, la, lb;
        split8(v0, v1, ha, hb, la, lb);
        *(uint2*)(smem + SA0 + aSt) = ha;
        *(uint2*)(smem + SA0 + aSt + 8) = hb;
        *(uint2*)(smem + SA1 + aSt) = la;
        *(uint2*)(smem + SA1 + aSt + 8) = lb;
        split8(v2, v3, ha, hb, la, lb);
        *(uint2*)(smem + SA0 + aSt + 16) = ha;
        *(uint2*)(smem + SA0 + aSt + 24) = hb;
        *(uint2*)(smem + SA1 + aSt + 16) = la;
        *(uint2*)(smem + SA1 + aSt + 24) = lb;
        CP_ASYNC16(sb + SB0 + bSt, w0p);
        CP_ASYNC16(sb + SB1 + bSt, w1p);
        CP_COMMIT();
    }
    CP_WAIT0();
    __syncthreads();

#pragma unroll 1
    for (int ck = 0; ck < 8; ++ck) {
        const uint32_t bufS = (uint32_t)(ck & 1) * BUFSZ;
        const uint32_t bufN = (uint32_t)((ck + 1) & 1) * BUFSZ;

        float4 v0, v1, v2, v3;
        if (ck < 7) {
            // issue next-chunk loads early
            v0 = *(const float4*)(xp + (ck + 1) * 32);
            v1 = *(const float4*)(xp + (ck + 1) * 32 + 4);
            v2 = *(const float4*)(xp + (ck + 1) * 32 + 8);
            v3 = *(const float4*)(xp + (ck + 1) * 32 + 12);
            CP_ASYNC16(sb + bufN + SB0 + bSt, w0p + (ck + 1) * 32);
            CP_ASYNC16(sb + bufN + SB1 + bSt, w1p + (ck + 1) * 32);
            CP_COMMIT();
        }

        // ---- MMA phase on current buffer: 2 k16 subchunks x 3 terms ----
        const uint32_t aRow = sb + bufS + aRowOff;
        const uint32_t bRow = sb + bufS + bRowOff;
#pragma unroll
        for (int s = 0; s < 2; ++s) {
            const uint32_t acol = (uint32_t)s * 32;
            uint32_t a[2][4], b0[2][4], b1[2][4];
            // A0 + B0 frags
#pragma unroll
            for (int mf = 0; mf < 2; ++mf) ldsm4(a[mf], aRow + acol + mf * 16 * APITCH);
#pragma unroll
            for (int p = 0; p < 2; ++p) ldsm4(b0[p], bRow + acol + p * 16 * APITCH);
            // term A0*B0
#pragma unroll
            for (int mf = 0; mf < 2; ++mf)
#pragma unroll
                for (int p = 0; p < 2; ++p) {
                    mma16816(c[mf][p * 2],     a[mf], &b0[p][0]);
                    mma16816(c[mf][p * 2 + 1], a[mf], &b0[p][2]);
                }
            // term A0*B1
#pragma unroll
            for (int p = 0; p < 2; ++p) ldsm4(b1[p], bRow + (SB1 - SB0) + acol + p * 16 * APITCH);
#pragma unroll
            for (int mf = 0; mf < 2; ++mf)
#pragma unroll
                for (int p = 0; p < 2; ++p) {
                    mma16816(c[mf][p * 2],     a[mf], &b1[p][0]);
                    mma16816(c[mf][p * 2 + 1], a[mf], &b1[p][2]);
                }
            // term A1*B0 (B0 frags still live in regs)
#pragma unroll
            for (int mf = 0; mf < 2; ++mf) ldsm4(a[mf], aRow + (SA1 - SA0) + acol + mf * 16 * APITCH);
#pragma unroll
            for (int mf = 0; mf < 2; ++mf)
#pragma unroll
                for (int p = 0; p < 2; ++p) {
                    mma16816(c[mf][p * 2],     a[mf], &b0[p][0]);
                    mma16816(c[mf][p * 2 + 1], a[mf], &b0[p][2]);
                }
        }

        // ---- stage A for next chunk into next buffer ----
        if (ck < 7) {
            uint2 ha, hb, la, lb;
            split8(v0, v1, ha, hb, la, lb);
            *(uint2*)(smem + bufN + SA0 + aSt) = ha;
            *(uint2*)(smem + bufN + SA0 + aSt + 8) = hb;
            *(uint2*)(smem + bufN + SA1 + aSt) = la;
            *(uint2*)(smem + bufN + SA1 + aSt + 8) = lb;
            split8(v2, v3, ha, hb, la, lb);
            *(uint2*)(smem + bufN + SA0 + aSt + 16) = ha;
            *(uint2*)(smem + bufN + SA0 + aSt + 24) = hb;
            *(uint2*)(smem + bufN + SA1 + aSt + 16) = la;
            *(uint2*)(smem + bufN + SA1 + aSt + 24) = lb;
        }
        CP_WAIT0();
        __syncthreads();
    }

    // ---- epilogue: bias + store ----
    const int ncol = gh * 256 + nq * 64 + wn + (lane & 3) * 2;
    const float* bp = Bias + ncol;
    const int mbase = bx * 128 + wm + (lane >> 2);
    float* gbase = g_gates + (size_t)mbase * 4096 + ncol;

#pragma unroll
    for (int nf = 0; nf < 4; ++nf) {
        float2 bv = *(const float2*)(bp + nf * 8);
#pragma unroll
        for (int mf = 0; mf < 2; ++mf) {
            float* p0 = gbase + (size_t)(mf * 16) * 4096 + nf * 8;
            float2 w0 = make_float2(c[mf][nf][0] + bv.x, c[mf][nf][1] + bv.y);
            float2 w1 = make_float2(c[mf][nf][2] + bv.x, c[mf][nf][3] + bv.y);
            *(float2*)p0 = w0;
            *(float2*)(p0 + 8 * 4096) = w1;
        }
    }
}

// ===========================================================================
// Scan phase 1: per-(channel, chunk) local reduction. CHUNK=64, NCHUNK=32.
// ===========================================================================
__global__ __launch_bounds__(256) void scan_local_kernel()
{
    const int ch = blockIdx.x * 256 + threadIdx.x;  // 0..4095
    const int k  = blockIdx.y;                      // chunk
    const int b  = ch >> 10;
    const int hd = ch & 1023;
    const float* gp = g_gates + (size_t)b * 2048 * 4096 + (size_t)k * CHUNK * 4096 + hd;

    float m = -1e30f, c = 0.f, n = 0.f, F = 0.f;

#pragma unroll 8
    for (int s = 0; s < CHUNK; ++s) {
        const float* row = gp + (size_t)s * 4096;
        float zb = __ldg(row);
        float ib = __ldg(row + 1024);
        float fb = __ldg(row + 2048);

        float zv = 1.f - __fdividef(2.f, __expf(2.f * zb) + 1.f);

        float lf = fb, li = ib;
        if (fminf(fb, ib) < -6.f) {
            lf = __logf(__expf(fb) + EPSV);
            li = __logf(__expf(ib) + EPSV);
        }
        F += lf;

        float mn = fmaxf(lf + m, li);
        float ih = __expf(li - mn);
        float fh = __expf(lf + m - mn);
        c = fmaf(fh, c, ih * zv);
        n = fmaf(fh, n, ih);
        m = mn;
    }
    g_cstate[(size_t)k * NCH + ch] = make_float4(F, m, c, n);
}

// ===========================================================================
// Scan phase 2: sequential combine with batch-of-8 register prefetch.
// ===========================================================================
__global__ __launch_bounds__(256) void scan_combine_kernel(float* __restrict__ Out)
{
    const int ch = blockIdx.x * 256 + threadIdx.x;  // 0..4095
    float m = 0.f, c = 0.f, n = 0.f;

#pragma unroll 1
    for (int k0 = 0; k0 < NCHUNK; k0 += 8) {
        float4 buf[8];
#pragma unroll
        for (int j = 0; j < 8; ++j)
            buf[j] = g_cstate[(size_t)(k0 + j) * NCH + ch];
#pragma unroll
        for (int j = 0; j < 8; ++j) {
            g_carry[(size_t)(k0 + j) * NCH + ch] = make_float4(m, c, n, 0.f);
            float4 st = buf[j];  // (F, m_loc, c_loc, n_loc)
            float mo = fmaxf(st.x + m, st.y);
            float ea = __expf(st.x + m - mo);
            float eb = __expf(st.y - mo);
            c = fmaf(ea, c, eb * st.z);
            n = fmaf(ea, n, eb * st.w);
            m = mo;
        }
    }
    Out[8388608 + 4096 + ch]  = c;   // c_f
    Out[8388608 + 8192 + ch]  = n;   // n_f
    Out[8388608 + 12288 + ch] = m;   // m_f
}

// ===========================================================================
// Scan phase 3: replay each chunk from its exact carry-in and emit h.
// ===========================================================================
__global__ __launch_bounds__(256) void scan_emit_kernel(float* __restrict__ Out)
{
    const int ch = blockIdx.x * 256 + threadIdx.x;
    const int k  = blockIdx.y;
    const int b  = ch >> 10;
    const int hd = ch & 1023;
    const float* gp = g_gates + (size_t)b * 2048 * 4096 + (size_t)k * CHUNK * 4096 + hd;
    float* hp = Out + (size_t)b * 2048 * 1024 + (size_t)k * CHUNK * 1024 + hd;

    float4 cr = g_carry[(size_t)k * NCH + ch];
    float m = cr.x, c = cr.y, n = cr.z, hv = 0.f;

#pragma unroll 8
    for (int s = 0; s < CHUNK; ++s) {
        const float* row = gp + (size_t)s * 4096;
        float zb = __ldg(row);
        float ib = __ldg(row + 1024);
        float fb = __ldg(row + 2048);
        float ob = __ldg(row + 3072);

        float zv = 1.f - __fdividef(2.f, __expf(2.f * zb) + 1.f);
        float ov = __fdividef(1.f, 1.f + __expf(-ob));

        float lf = fb, li = ib;
        if (fminf(fb, ib) < -6.f) {
            lf = __logf(__expf(fb) + EPSV);
            li = __logf(__expf(ib) + EPSV);
        }

        float mn = fmaxf(lf + m, li);
        float ih = __expf(li - mn);
        float fh = __expf(lf + m - mn);
        c = fmaf(fh, c, ih * zv);
        n = fmaf(fh, n, ih);
        m = mn;
        hv = ov * __fdividef(c, n + EPSV);
        hp[(size_t)s * 1024] = hv;
    }

    if (k == NCHUNK - 1) Out[8388608 + ch] = hv;  // h_f
}

// ---------------------------------------------------------------------------
extern "C" void kernel_launch(void* const* d_in, const int* in_sizes, int n_in,
                              void* d_out, int out_size)
{
    const float* X  = (const float*)d_in[0];  // [4, 2048, 4096]
    const float* W  = (const float*)d_in[1];  // [4, 4, 256, 256]
    const float* Bv = (const float*)d_in[2];  // [4, 4, 256]
    float* out = (float*)d_out;

    cudaFuncSetAttribute(gemm_mma_kernel, cudaFuncAttributeMaxDynamicSharedMemorySize,
                         SMEM_GEMM);

    wsplit_kernel<<<1024, 256>>>(W);
    gemm_mma_kernel<<<dim3(64, 64), 256, SMEM_GEMM>>>(X, Bv);
    scan_local_kernel<<<dim3(16, NCHUNK), 256>>>();
    scan_combine_kernel<<<16, 256>>>(out);
    scan_emit_kernel<<<dim3(16, NCHUNK), 256>>>(out);
}

// round 12
// speedup vs baseline: 1.0237x; 1.0237x over previous
#include <cuda_runtime.h>
#include <cuda_fp16.h>
#include <cstdint>
#include <cstddef>

#define EPSV 1e-8f
#define CHUNK 64
#define NCHUNK 32
#define NCH 4096  // channels = B*NH*HD

// Gate pre-activations scratch: [B=4][S=2048][4 gates][NH=4][HD=256] fp32 = 128 MiB
static __device__ float g_gates[33554432];
// per-(chunk,channel) local state (F, m_loc, c_loc, n_loc)
static __device__ float4 g_cstate[NCHUNK * NCH];
// per-(chunk,channel) carry-in state (m, c, n, -)
static __device__ float4 g_carry[NCHUNK * NCH];
// Pre-split weights: fp16 hi/lo, layout [gh][n][k] like W
static __device__ __half g_W0[1048576];
static __device__ __half g_W1[1048576];

// ---------------------------------------------------------------------------
__device__ __forceinline__ uint32_t smem_u32(const void* p) {
    uint32_t a;
    asm("{ .reg .u64 t; cvta.to.shared.u64 t, %1; cvt.u32.u64 %0, t; }" : "=r"(a) : "l"(p));
    return a;
}
__device__ __forceinline__ void ldsm4(uint32_t* r, uint32_t addr) {
    asm volatile("ldmatrix.sync.aligned.m8n8.x4.shared.b16 {%0,%1,%2,%3}, [%4];"
                 : "=r"(r[0]), "=r"(r[1]), "=r"(r[2]), "=r"(r[3]) : "r"(addr));
}
// fp32-accum f16 MMA (main term)
__device__ __forceinline__ void mma_f32(float* c, const uint32_t* a, const uint32_t* b) {
    asm volatile(
        "mma.sync.aligned.m16n8k16.row.col.f32.f16.f16.f32 "
        "{%0,%1,%2,%3}, {%4,%5,%6,%7}, {%8,%9}, {%0,%1,%2,%3};"
        : "+f"(c[0]), "+f"(c[1]), "+f"(c[2]), "+f"(c[3])
        : "r"(a[0]), "r"(a[1]), "r"(a[2]), "r"(a[3]), "r"(b[0]), "r"(b[1]));
}
// fp16-accum f16 MMA (correction terms, 2x rate)
__device__ __forceinline__ void mma_f16(uint32_t* d, const uint32_t* a, const uint32_t* b) {
    asm volatile(
        "mma.sync.aligned.m16n8k16.row.col.f16.f16.f16.f16 "
        "{%0,%1}, {%2,%3,%4,%5}, {%6,%7}, {%0,%1};"
        : "+r"(d[0]), "+r"(d[1])
        : "r"(a[0]), "r"(a[1]), "r"(a[2]), "r"(a[3]), "r"(b[0]), "r"(b[1]));
}
#define CP_ASYNC16(sa, gp) \
    asm volatile("cp.async.ca.shared.global [%0], [%1], 16;" :: "r"(sa), "l"(gp))
#define CP_COMMIT() asm volatile("cp.async.commit_group;" ::: "memory")
#define CP_WAIT0()  asm volatile("cp.async.wait_group 0;" ::: "memory")

// convert 8 fp32 -> fp16 hi (uint2 x2) + lo (uint2 x2)
__device__ __forceinline__ void split8(const float4& v0, const float4& v1,
                                       uint2& h_a, uint2& h_b, uint2& l_a, uint2& l_b) {
    __half2 h0 = __floats2half2_rn(v0.x, v0.y);
    __half2 h1 = __floats2half2_rn(v0.z, v0.w);
    __half2 h2 = __floats2half2_rn(v1.x, v1.y);
    __half2 h3 = __floats2half2_rn(v1.z, v1.w);
    float2 f0 = __half22float2(h0), f1 = __half22float2(h1);
    float2 f2 = __half22float2(h2), f3 = __half22float2(h3);
    __half2 l0 = __floats2half2_rn(v0.x - f0.x, v0.y - f0.y);
    __half2 l1 = __floats2half2_rn(v0.z - f1.x, v0.w - f1.y);
    __half2 l2 = __floats2half2_rn(v1.x - f2.x, v1.y - f2.y);
    __half2 l3 = __floats2half2_rn(v1.z - f3.x, v1.w - f3.y);
    h_a.x = *(const uint32_t*)&h0; h_a.y = *(const uint32_t*)&h1;
    h_b.x = *(const uint32_t*)&h2; h_b.y = *(const uint32_t*)&h3;
    l_a.x = *(const uint32_t*)&l0; l_a.y = *(const uint32_t*)&l1;
    l_b.x = *(const uint32_t*)&l2; l_b.y = *(const uint32_t*)&l3;
}

// ===========================================================================
// Kernel 0: pre-split W (fp32 -> fp16 hi + fp16 lo). 1,048,576 elements.
// ===========================================================================
__global__ __launch_bounds__(256) void wsplit_kernel(const float* __restrict__ W)
{
    const int i = blockIdx.x * 256 + threadIdx.x;  // float4 id, 262144 total
    float4 v = *(const float4*)(W + (size_t)i * 4);
    __half2 h0 = __floats2half2_rn(v.x, v.y);
    __half2 h1 = __floats2half2_rn(v.z, v.w);
    float2 f0 = __half22float2(h0), f1 = __half22float2(h1);
    __half2 l0 = __floats2half2_rn(v.x - f0.x, v.y - f0.y);
    __half2 l1 = __floats2half2_rn(v.z - f1.x, v.w - f1.y);
    uint2 ha, la;
    ha.x = *(const uint32_t*)&h0; ha.y = *(const uint32_t*)&h1;
    la.x = *(const uint32_t*)&l0; la.y = *(const uint32_t*)&l1;
    *(uint2*)&g_W0[(size_t)i * 4] = ha;
    *(uint2*)&g_W1[(size_t)i * 4] = la;
}

// ===========================================================================
// Kernel 1: block-diagonal GEMM via mma.sync fp16 2-split:
//   main term fp32-accum, correction terms fp16-accum (2x rate).
//   grid (64 m-tiles, 16 gh), 512 threads = 16 warps (2 m x 8 n),
//   warp tile 64x32. K=256 in 8 chunks of 32. (R8 skeleton.)
//   A: LDG->convert->STS double-buffered. B: cp.async double-buffered.
//   smem rows: 32 fp16 (64B) + 16B pad = 80B pitch (conflict-free ldmatrix).
// ===========================================================================
#define APITCH 80
#define SA0 0            // 128 rows * 80B = 10240
#define SA1 10240
#define SB0 20480        // 256 rows * 80B = 20480
#define SB1 40960
#define BUFSZ 61440
#define SMEM_GEMM (2 * BUFSZ)

__global__ __launch_bounds__(512) void gemm_mma_kernel(
    const float* __restrict__ X, const float* __restrict__ Bias)
{
    extern __shared__ __align__(16) char smem[];
    const uint32_t sb = smem_u32(smem);

    const int tid  = threadIdx.x;
    const int lane = tid & 31;
    const int wid  = tid >> 5;
    const int wm   = (wid & 1) * 64;   // warp m offset
    const int wn   = (wid >> 1) * 32;  // warp n offset
    const int bx   = blockIdx.x;
    const int gh   = blockIdx.y;

    float c[4][4][4];
#pragma unroll
    for (int i = 0; i < 4; ++i)
#pragma unroll
        for (int j = 0; j < 4; ++j)
#pragma unroll
            for (int q = 0; q < 4; ++q) c[i][j][q] = 0.f;
    uint32_t c16[4][4][2];
#pragma unroll
    for (int i = 0; i < 4; ++i)
#pragma unroll
        for (int j = 0; j < 4; ++j) { c16[i][j][0] = 0u; c16[i][j][1] = 0u; }

    // ---- staging assignments ----
    // A: thread -> row (tid>>2) [0..127], col group (tid&3)*8 floats of 32
    const float* xp = X + (size_t)(bx * 128 + (tid >> 2)) * 4096 + gh * 256 + (tid & 3) * 8;
    const uint32_t aSt0 = (uint32_t)(tid >> 2) * APITCH + (tid & 3) * 16;  // fp16: 8 elems=16B
    // B: thread -> row (tid>>1) [0..255], 32B half (tid&1)
    const __half* w0p = g_W0 + (size_t)gh * 65536 + (size_t)(tid >> 1) * 256 + (tid & 1) * 16;
    const __half* w1p = g_W1 + (size_t)gh * 65536 + (size_t)(tid >> 1) * 256 + (tid & 1) * 16;
    const uint32_t bSt = (uint32_t)(tid >> 1) * APITCH + (tid & 1) * 32;

    // ldmatrix base offsets (within a buffer)
    const uint32_t aRowOff = SA0 + (uint32_t)(wm + (lane & 15)) * APITCH + (lane >> 4) * 16;
    const uint32_t bRowOff = SB0 + (uint32_t)(wn + (lane & 7) + (lane >> 4) * 8) * APITCH
                           + ((lane >> 3) & 1) * 16;

    // ---- prologue: stage chunk 0 into buffer 0 ----
    {
        float4 v0 = *(const float4*)xp;
        float4 v1 = *(const float4*)(xp + 4);
        uint2 ha, hb, la, lb;
        split8(v0, v1, ha, hb, la, lb);
        *(uint2*)(smem + SA0 + aSt0) = ha;
        *(uint2*)(smem + SA0 + aSt0 + 8) = hb;
        *(uint2*)(smem + SA1 + aSt0) = la;
        *(uint2*)(smem + SA1 + aSt0 + 8) = lb;
        CP_ASYNC16(sb + SB0 + bSt,      w0p);
        CP_ASYNC16(sb + SB0 + bSt + 16, w0p + 8);
        CP_ASYNC16(sb + SB1 + bSt,      w1p);
        CP_ASYNC16(sb + SB1 + bSt + 16, w1p + 8);
        CP_COMMIT();
    }
    CP_WAIT0();
    __syncthreads();

#pragma unroll 1
    for (int ck = 0; ck < 8; ++ck) {
        const uint32_t bufS = (uint32_t)(ck & 1) * BUFSZ;
        const uint32_t bufN = (uint32_t)((ck + 1) & 1) * BUFSZ;

        float4 v0, v1;
        if (ck < 7) {
            // issue next-chunk loads early
            v0 = *(const float4*)(xp + (ck + 1) * 32);
            v1 = *(const float4*)(xp + (ck + 1) * 32 + 4);
            CP_ASYNC16(sb + bufN + SB0 + bSt,      w0p + (ck + 1) * 32);
            CP_ASYNC16(sb + bufN + SB0 + bSt + 16, w0p + (ck + 1) * 32 + 8);
            CP_ASYNC16(sb + bufN + SB1 + bSt,      w1p + (ck + 1) * 32);
            CP_ASYNC16(sb + bufN + SB1 + bSt + 16, w1p + (ck + 1) * 32 + 8);
            CP_COMMIT();
        }

        // ---- MMA phase on current buffer: 2 k16 subchunks ----
        const uint32_t aRow = sb + bufS + aRowOff;
        const uint32_t bRow = sb + bufS + bRowOff;
#pragma unroll
        for (int s = 0; s < 2; ++s) {
            const uint32_t acol = (uint32_t)s * 32;
            uint32_t a[4][4], b[2][4];
            // A0 + B0 frags
#pragma unroll
            for (int mf = 0; mf < 4; ++mf) ldsm4(a[mf], aRow + acol + mf * 16 * APITCH);
#pragma unroll
            for (int p = 0; p < 2; ++p) ldsm4(b[p], bRow + acol + p * 16 * APITCH);
            // main term A0*B0 (fp32 accum)
#pragma unroll
            for (int mf = 0; mf < 4; ++mf)
#pragma unroll
                for (int p = 0; p < 2; ++p) {
                    mma_f32(c[mf][p * 2],     a[mf], &b[p][0]);
                    mma_f32(c[mf][p * 2 + 1], a[mf], &b[p][2]);
                }
            // correction A0*B1 (fp16 accum, 2x rate)
#pragma unroll
            for (int p = 0; p < 2; ++p) ldsm4(b[p], bRow + 20480 + acol + p * 16 * APITCH);
#pragma unroll
            for (int mf = 0; mf < 4; ++mf)
#pragma unroll
                for (int p = 0; p < 2; ++p) {
                    mma_f16(c16[mf][p * 2],     a[mf], &b[p][0]);
                    mma_f16(c16[mf][p * 2 + 1], a[mf], &b[p][2]);
                }
            // correction A1*B0 (fp16 accum, 2x rate)
#pragma unroll
            for (int mf = 0; mf < 4; ++mf) ldsm4(a[mf], aRow + 10240 + acol + mf * 16 * APITCH);
#pragma unroll
            for (int p = 0; p < 2; ++p) ldsm4(b[p], bRow + acol + p * 16 * APITCH);
#pragma unroll
            for (int mf = 0; mf < 4; ++mf)
#pragma unroll
                for (int p = 0; p < 2; ++p) {
                    mma_f16(c16[mf][p * 2],     a[mf], &b[p][0]);
                    mma_f16(c16[mf][p * 2 + 1], a[mf], &b[p][2]);
                }
        }

        // ---- stage A for next chunk into next buffer ----
        if (ck < 7) {
            uint2 ha, hb, la, lb;
            split8(v0, v1, ha, hb, la, lb);
            *(uint2*)(smem + bufN + SA0 + aSt0) = ha;
            *(uint2*)(smem + bufN + SA0 + aSt0 + 8) = hb;
            *(uint2*)(smem + bufN + SA1 + aSt0) = la;
            *(uint2*)(smem + bufN + SA1 + aSt0 + 8) = lb;
        }
        CP_WAIT0();
        __syncthreads();
    }

    // ---- epilogue: fold fp16 corrections + bias + store ----
    const float* bp = Bias + gh * 256 + wn + (lane & 3) * 2;
    const int mbase = bx * 128 + wm + (lane >> 2);
    float* gbase = g_gates + (size_t)mbase * 4096 + gh * 256 + wn + (lane & 3) * 2;

#pragma unroll
    for (int nf = 0; nf < 4; ++nf) {
        float2 bv = *(const float2*)(bp + nf * 8);
#pragma unroll
        for (int mf = 0; mf < 4; ++mf) {
            float2 corr0 = __half22float2(*(const __half2*)&c16[mf][nf][0]);
            float2 corr1 = __half22float2(*(const __half2*)&c16[mf][nf][1]);
            float* p0 = gbase + (size_t)(mf * 16) * 4096 + nf * 8;
            float2 w0 = make_float2(c[mf][nf][0] + corr0.x + bv.x,
                                    c[mf][nf][1] + corr0.y + bv.y);
            float2 w1 = make_float2(c[mf][nf][2] + corr1.x + bv.x,
                                    c[mf][nf][3] + corr1.y + bv.y);
            *(float2*)p0 = w0;
            *(float2*)(p0 + 8 * 4096) = w1;
        }
    }
}

// ===========================================================================
// Scan phase 1: per-(channel, chunk) local reduction. CHUNK=64, NCHUNK=32.
// ===========================================================================
__global__ __launch_bounds__(256) void scan_local_kernel()
{
    const int ch = blockIdx.x * 256 + threadIdx.x;  // 0..4095
    const int k  = blockIdx.y;                      // chunk
    const int b  = ch >> 10;
    const int hd = ch & 1023;
    const float* gp = g_gates + (size_t)b * 2048 * 4096 + (size_t)k * CHUNK * 4096 + hd;

    float m = -1e30f, c = 0.f, n = 0.f, F = 0.f;

#pragma unroll 8
    for (int s = 0; s < CHUNK; ++s) {
        const float* row = gp + (size_t)s * 4096;
        float zb = __ldg(row);
        float ib = __ldg(row + 1024);
        float fb = __ldg(row + 2048);

        float zv = 1.f - __fdividef(2.f, __expf(2.f * zb) + 1.f);

        float lf = fb, li = ib;
        if (fminf(fb, ib) < -6.f) {
            lf = __logf(__expf(fb) + EPSV);
            li = __logf(__expf(ib) + EPSV);
        }
        F += lf;

        float mn = fmaxf(lf + m, li);
        float ih = __expf(li - mn);
        float fh = __expf(lf + m - mn);
        c = fmaf(fh, c, ih * zv);
        n = fmaf(fh, n, ih);
        m = mn;
    }
    g_cstate[(size_t)k * NCH + ch] = make_float4(F, m, c, n);
}

// ===========================================================================
// Scan phase 2: sequential combine with batch-of-8 register prefetch.
// ===========================================================================
__global__ __launch_bounds__(256) void scan_combine_kernel(float* __restrict__ Out)
{
    const int ch = blockIdx.x * 256 + threadIdx.x;  // 0..4095
    float m = 0.f, c = 0.f, n = 0.f;

#pragma unroll 1
    for (int k0 = 0; k0 < NCHUNK; k0 += 8) {
        float4 buf[8];
#pragma unroll
        for (int j = 0; j < 8; ++j)
            buf[j] = g_cstate[(size_t)(k0 + j) * NCH + ch];
#pragma unroll
        for (int j = 0; j < 8; ++j) {
            g_carry[(size_t)(k0 + j) * NCH + ch] = make_float4(m, c, n, 0.f);
            float4 st = buf[j];  // (F, m_loc, c_loc, n_loc)
            float mo = fmaxf(st.x + m, st.y);
            float ea = __expf(st.x + m - mo);
            float eb = __expf(st.y - mo);
            c = fmaf(ea, c, eb * st.z);
            n = fmaf(ea, n, eb * st.w);
            m = mo;
        }
    }
    Out[8388608 + 4096 + ch]  = c;   // c_f
    Out[8388608 + 8192 + ch]  = n;   // n_f
    Out[8388608 + 12288 + ch] = m;   // m_f
}

// ===========================================================================
// Scan phase 3: replay each chunk from its exact carry-in and emit h.
// ===========================================================================
__global__ __launch_bounds__(256) void scan_emit_kernel(float* __restrict__ Out)
{
    const int ch = blockIdx.x * 256 + threadIdx.x;
    const int k  = blockIdx.y;
    const int b  = ch >> 10;
    const int hd = ch & 1023;
    const float* gp = g_gates + (size_t)b * 2048 * 4096 + (size_t)k * CHUNK * 4096 + hd;
    float* hp = Out + (size_t)b * 2048 * 1024 + (size_t)k * CHUNK * 1024 + hd;

    float4 cr = g_carry[(size_t)k * NCH + ch];
    float m = cr.x, c = cr.y, n = cr.z, hv = 0.f;

#pragma unroll 8
    for (int s = 0; s < CHUNK; ++s) {
        const float* row = gp + (size_t)s * 4096;
        float zb = __ldg(row);
        float ib = __ldg(row + 1024);
        float fb = __ldg(row + 2048);
        float ob = __ldg(row + 3072);

        float zv = 1.f - __fdividef(2.f, __expf(2.f * zb) + 1.f);
        float ov = __fdividef(1.f, 1.f + __expf(-ob));

        float lf = fb, li = ib;
        if (fminf(fb, ib) < -6.f) {
            lf = __logf(__expf(fb) + EPSV);
            li = __logf(__expf(ib) + EPSV);
        }

        float mn = fmaxf(lf + m, li);
        float ih = __expf(li - mn);
        float fh = __expf(lf + m - mn);
        c = fmaf(fh, c, ih * zv);
        n = fmaf(fh, n, ih);
        m = mn;
        hv = ov * __fdividef(c, n + EPSV);
        hp[(size_t)s * 1024] = hv;
    }

    if (k == NCHUNK - 1) Out[8388608 + ch] = hv;  // h_f
}

// ---------------------------------------------------------------------------
extern "C" void kernel_launch(void* const* d_in, const int* in_sizes, int n_in,
                              void* d_out, int out_size)
{
    const float* X  = (const float*)d_in[0];  // [4, 2048, 4096]
    const float* W  = (const float*)d_in[1];  // [4, 4, 256, 256]
    const float* Bv = (const float*)d_in[2];  // [4, 4, 256]
    float* out = (float*)d_out;

    cudaFuncSetAttribute(gemm_mma_kernel, cudaFuncAttributeMaxDynamicSharedMemorySize,
                         SMEM_GEMM);

    wsplit_kernel<<<1024, 256>>>(W);
    gemm_mma_kernel<<<dim3(64, 16), 512, SMEM_GEMM>>>(X, Bv);
    scan_local_kernel<<<dim3(16, NCHUNK), 256>>>();
    scan_combine_kernel<<<16, 256>>>(out);
    scan_emit_kernel<<<dim3(16, NCHUNK), 256>>>(out);
}

// round 13
// speedup vs baseline: 1.4402x; 1.4068x over previous
#include <cuda_runtime.h>
#include <cuda_fp16.h>
#include <cstdint>
#include <cstddef>

#define EPSV 1e-8f
#define CHUNK 64
#define NCHUNK 32
#define NCH 4096  // channels = B*NH*HD

// Gate pre-activations scratch: [B=4][S=2048][4 gates][NH=4][HD=256] fp32 = 128 MiB
static __device__ float g_gates[33554432];
// per-(chunk,channel) local state (F, m_loc, c_loc, n_loc)
static __device__ float4 g_cstate[NCHUNK * NCH];
// per-(chunk,channel) carry-in state (m, c, n, -)
static __device__ float4 g_carry[NCHUNK * NCH];
// Pre-split weights: fp16 hi/lo, layout [gh][n][k] like W
static __device__ __half g_W0[1048576];
static __device__ __half g_W1[1048576];

// ---------------------------------------------------------------------------
__device__ __forceinline__ uint32_t smem_u32(const void* p) {
    uint32_t a;
    asm("{ .reg .u64 t; cvta.to.shared.u64 t, %1; cvt.u32.u64 %0, t; }" : "=r"(a) : "l"(p));
    return a;
}
__device__ __forceinline__ void ldsm4(uint32_t* r, uint32_t addr) {
    asm volatile("ldmatrix.sync.aligned.m8n8.x4.shared.b16 {%0,%1,%2,%3}, [%4];"
                 : "=r"(r[0]), "=r"(r[1]), "=r"(r[2]), "=r"(r[3]) : "r"(addr));
}
__device__ __forceinline__ void mma16816(float* c, const uint32_t* a, const uint32_t* b) {
    asm volatile(
        "mma.sync.aligned.m16n8k16.row.col.f32.f16.f16.f32 "
        "{%0,%1,%2,%3}, {%4,%5,%6,%7}, {%8,%9}, {%0,%1,%2,%3};"
        : "+f"(c[0]), "+f"(c[1]), "+f"(c[2]), "+f"(c[3])
        : "r"(a[0]), "r"(a[1]), "r"(a[2]), "r"(a[3]), "r"(b[0]), "r"(b[1]));
}
#define CP_ASYNC16(sa, gp) \
    asm volatile("cp.async.ca.shared.global [%0], [%1], 16;" :: "r"(sa), "l"(gp))
#define CP_COMMIT() asm volatile("cp.async.commit_group;" ::: "memory")
#define CP_WAIT0()  asm volatile("cp.async.wait_group 0;" ::: "memory")

// convert 8 fp32 -> fp16 hi (uint2 x2) + lo (uint2 x2)
__device__ __forceinline__ void split8(const float4& v0, const float4& v1,
                                       uint2& h_a, uint2& h_b, uint2& l_a, uint2& l_b) {
    __half2 h0 = __floats2half2_rn(v0.x, v0.y);
    __half2 h1 = __floats2half2_rn(v0.z, v0.w);
    __half2 h2 = __floats2half2_rn(v1.x, v1.y);
    __half2 h3 = __floats2half2_rn(v1.z, v1.w);
    float2 f0 = __half22float2(h0), f1 = __half22float2(h1);
    float2 f2 = __half22float2(h2), f3 = __half22float2(h3);
    __half2 l0 = __floats2half2_rn(v0.x - f0.x, v0.y - f0.y);
    __half2 l1 = __floats2half2_rn(v0.z - f1.x, v0.w - f1.y);
    __half2 l2 = __floats2half2_rn(v1.x - f2.x, v1.y - f2.y);
    __half2 l3 = __floats2half2_rn(v1.z - f3.x, v1.w - f3.y);
    h_a.x = *(const uint32_t*)&h0; h_a.y = *(const uint32_t*)&h1;
    h_b.x = *(const uint32_t*)&h2; h_b.y = *(const uint32_t*)&h3;
    l_a.x = *(const uint32_t*)&l0; l_a.y = *(const uint32_t*)&l1;
    l_b.x = *(const uint32_t*)&l2; l_b.y = *(const uint32_t*)&l3;
}
// hi-only convert
__device__ __forceinline__ void hi8(const float4& v0, const float4& v1,
                                    uint2& h_a, uint2& h_b) {
    __half2 h0 = __floats2half2_rn(v0.x, v0.y);
    __half2 h1 = __floats2half2_rn(v0.z, v0.w);
    __half2 h2 = __floats2half2_rn(v1.x, v1.y);
    __half2 h3 = __floats2half2_rn(v1.z, v1.w);
    h_a.x = *(const uint32_t*)&h0; h_a.y = *(const uint32_t*)&h1;
    h_b.x = *(const uint32_t*)&h2; h_b.y = *(const uint32_t*)&h3;
}

// ===========================================================================
// Kernel 0: pre-split W (fp32 -> fp16 hi + fp16 lo). 1,048,576 elements.
// ===========================================================================
__global__ __launch_bounds__(256) void wsplit_kernel(const float* __restrict__ W)
{
    const int i = blockIdx.x * 256 + threadIdx.x;  // float4 id, 262144 total
    float4 v = *(const float4*)(W + (size_t)i * 4);
    __half2 h0 = __floats2half2_rn(v.x, v.y);
    __half2 h1 = __floats2half2_rn(v.z, v.w);
    float2 f0 = __half22float2(h0), f1 = __half22float2(h1);
    __half2 l0 = __floats2half2_rn(v.x - f0.x, v.y - f0.y);
    __half2 l1 = __floats2half2_rn(v.z - f1.x, v.w - f1.y);
    uint2 ha, la;
    ha.x = *(const uint32_t*)&h0; ha.y = *(const uint32_t*)&h1;
    la.x = *(const uint32_t*)&l0; la.y = *(const uint32_t*)&l1;
    *(uint2*)&g_W0[(size_t)i * 4] = ha;
    *(uint2*)&g_W1[(size_t)i * 4] = la;
}

// ===========================================================================
// Kernel 1: block-diagonal GEMM via mma.sync fp16.
//   Per-gate precision: f gate (g==2) uses 3-term 2-split (full fp32-equiv);
//   z,i,o gates use single-term fp16 (their errors don't accumulate in the
//   scan). Halves total MMA work vs uniform 3-term.
//   grid (64 m-tiles, 16 = 4 g x 4 h, g fastest for wave balance),
//   512 threads = 16 warps (2 m x 8 n), warp tile 64x32. K=256, 8 chunks of 32.
//   A: LDG->convert->STS double-buffered. B: cp.async double-buffered.
//   smem rows: 32 fp16 (64B) + 16B pad = 80B pitch (conflict-free ldmatrix).
// ===========================================================================
#define APITCH 80
#define SA0 0            // 128 rows * 80B = 10240
#define SA1 10240
#define SB0 20480        // 256 rows * 80B = 20480
#define SB1 40960
#define BUFSZ 61440
#define SMEM_GEMM (2 * BUFSZ)

__global__ __launch_bounds__(512) void gemm_mma_kernel(
    const float* __restrict__ X, const float* __restrict__ Bias)
{
    extern __shared__ __align__(16) char smem[];
    const uint32_t sb = smem_u32(smem);

    const int tid  = threadIdx.x;
    const int lane = tid & 31;
    const int wid  = tid >> 5;
    const int wm   = (wid & 1) * 64;   // warp m offset
    const int wn   = (wid >> 1) * 32;  // warp n offset
    const int bx   = blockIdx.x;
    const int g    = blockIdx.y & 3;   // gate (varies fastest across bids)
    const int hh   = blockIdx.y >> 2;  // head
    const int ghm  = g * 4 + hh;       // memory index [gate][head]
    const bool full = (g == 2);        // f gate: 3-term split

    float c[4][4][4];
#pragma unroll
    for (int i = 0; i < 4; ++i)
#pragma unroll
        for (int j = 0; j < 4; ++j)
#pragma unroll
            for (int q = 0; q < 4; ++q) c[i][j][q] = 0.f;

    // ---- staging assignments ----
    const float* xp = X + (size_t)(bx * 128 + (tid >> 2)) * 4096 + ghm * 256 + (tid & 3) * 8;
    const uint32_t aSt0 = (uint32_t)(tid >> 2) * APITCH + (tid & 3) * 16;
    const __half* w0p = g_W0 + (size_t)ghm * 65536 + (size_t)(tid >> 1) * 256 + (tid & 1) * 16;
    const __half* w1p = g_W1 + (size_t)ghm * 65536 + (size_t)(tid >> 1) * 256 + (tid & 1) * 16;
    const uint32_t bSt = (uint32_t)(tid >> 1) * APITCH + (tid & 1) * 32;

    // ldmatrix base offsets (within a buffer)
    const uint32_t aRowOff = SA0 + (uint32_t)(wm + (lane & 15)) * APITCH + (lane >> 4) * 16;
    const uint32_t bRowOff = SB0 + (uint32_t)(wn + (lane & 7) + (lane >> 4) * 8) * APITCH
                           + ((lane >> 3) & 1) * 16;

    // ---- prologue: stage chunk 0 into buffer 0 ----
    {
        float4 v0 = *(const float4*)xp;
        float4 v1 = *(const float4*)(xp + 4);
        if (full) {
            uint2 ha, hb, la, lb;
            split8(v0, v1, ha, hb, la, lb);
            *(uint2*)(smem + SA0 + aSt0) = ha;
            *(uint2*)(smem + SA0 + aSt0 + 8) = hb;
            *(uint2*)(smem + SA1 + aSt0) = la;
            *(uint2*)(smem + SA1 + aSt0 + 8) = lb;
            CP_ASYNC16(sb + SB1 + bSt,      w1p);
            CP_ASYNC16(sb + SB1 + bSt + 16, w1p + 8);
        } else {
            uint2 ha, hb;
            hi8(v0, v1, ha, hb);
            *(uint2*)(smem + SA0 + aSt0) = ha;
            *(uint2*)(smem + SA0 + aSt0 + 8) = hb;
        }
        CP_ASYNC16(sb + SB0 + bSt,      w0p);
        CP_ASYNC16(sb + SB0 + bSt + 16, w0p + 8);
        CP_COMMIT();
    }
    CP_WAIT0();
    __syncthreads();

#pragma unroll 1
    for (int ck = 0; ck < 8; ++ck) {
        const uint32_t bufS = (uint32_t)(ck & 1) * BUFSZ;
        const uint32_t bufN = (uint32_t)((ck + 1) & 1) * BUFSZ;

        float4 v0, v1;
        if (ck < 7) {
            v0 = *(const float4*)(xp + (ck + 1) * 32);
            v1 = *(const float4*)(xp + (ck + 1) * 32 + 4);
            CP_ASYNC16(sb + bufN + SB0 + bSt,      w0p + (ck + 1) * 32);
            CP_ASYNC16(sb + bufN + SB0 + bSt + 16, w0p + (ck + 1) * 32 + 8);
            if (full) {
                CP_ASYNC16(sb + bufN + SB1 + bSt,      w1p + (ck + 1) * 32);
                CP_ASYNC16(sb + bufN + SB1 + bSt + 16, w1p + (ck + 1) * 32 + 8);
            }
            CP_COMMIT();
        }

        // ---- MMA phase: 2 k16 subchunks; f gate adds 2 correction terms ----
        const uint32_t aRow = sb + bufS + aRowOff;
        const uint32_t bRow = sb + bufS + bRowOff;
#pragma unroll
        for (int s = 0; s < 2; ++s) {
            const uint32_t acol = (uint32_t)s * 32;
            uint32_t a[4][4], b[2][4];
            // A0 + B0 frags, main term
#pragma unroll
            for (int mf = 0; mf < 4; ++mf) ldsm4(a[mf], aRow + acol + mf * 16 * APITCH);
#pragma unroll
            for (int p = 0; p < 2; ++p) ldsm4(b[p], bRow + acol + p * 16 * APITCH);
#pragma unroll
            for (int mf = 0; mf < 4; ++mf)
#pragma unroll
                for (int p = 0; p < 2; ++p) {
                    mma16816(c[mf][p * 2],     a[mf], &b[p][0]);
                    mma16816(c[mf][p * 2 + 1], a[mf], &b[p][2]);
                }
            if (full) {
                // term A0*B1
#pragma unroll
                for (int p = 0; p < 2; ++p) ldsm4(b[p], bRow + (SB1 - SB0) + acol + p * 16 * APITCH);
#pragma unroll
                for (int mf = 0; mf < 4; ++mf)
#pragma unroll
                    for (int p = 0; p < 2; ++p) {
                        mma16816(c[mf][p * 2],     a[mf], &b[p][0]);
                        mma16816(c[mf][p * 2 + 1], a[mf], &b[p][2]);
                    }
                // term A1*B0
#pragma unroll
                for (int mf = 0; mf < 4; ++mf) ldsm4(a[mf], aRow + (SA1 - SA0) + acol + mf * 16 * APITCH);
#pragma unroll
                for (int p = 0; p < 2; ++p) ldsm4(b[p], bRow + acol + p * 16 * APITCH);
#pragma unroll
                for (int mf = 0; mf < 4; ++mf)
#pragma unroll
                    for (int p = 0; p < 2; ++p) {
                        mma16816(c[mf][p * 2],     a[mf], &b[p][0]);
                        mma16816(c[mf][p * 2 + 1], a[mf], &b[p][2]);
                    }
            }
        }

        // ---- stage A for next chunk into next buffer ----
        if (ck < 7) {
            if (full) {
                uint2 ha, hb, la, lb;
                split8(v0, v1, ha, hb, la, lb);
                *(uint2*)(smem + bufN + SA0 + aSt0) = ha;
                *(uint2*)(smem + bufN + SA0 + aSt0 + 8) = hb;
                *(uint2*)(smem + bufN + SA1 + aSt0) = la;
                *(uint2*)(smem + bufN + SA1 + aSt0 + 8) = lb;
            } else {
                uint2 ha, hb;
                hi8(v0, v1, ha, hb);
                *(uint2*)(smem + bufN + SA0 + aSt0) = ha;
                *(uint2*)(smem + bufN + SA0 + aSt0 + 8) = hb;
            }
        }
        CP_WAIT0();
        __syncthreads();
    }

    // ---- epilogue: bias + store ----
    const float* bp = Bias + ghm * 256 + wn + (lane & 3) * 2;
    const int mbase = bx * 128 + wm + (lane >> 2);
    float* gbase = g_gates + (size_t)mbase * 4096 + ghm * 256 + wn + (lane & 3) * 2;

#pragma unroll
    for (int nf = 0; nf < 4; ++nf) {
        float2 bv = *(const float2*)(bp + nf * 8);
#pragma unroll
        for (int mf = 0; mf < 4; ++mf) {
            float* p0 = gbase + (size_t)(mf * 16) * 4096 + nf * 8;
            float2 w0 = make_float2(c[mf][nf][0] + bv.x, c[mf][nf][1] + bv.y);
            float2 w1 = make_float2(c[mf][nf][2] + bv.x, c[mf][nf][3] + bv.y);
            *(float2*)p0 = w0;
            *(float2*)(p0 + 8 * 4096) = w1;
        }
    }
}

// ===========================================================================
// Scan phase 1: per-(channel, chunk) local reduction. CHUNK=64, NCHUNK=32.
// ===========================================================================
__global__ __launch_bounds__(256) void scan_local_kernel()
{
    const int ch = blockIdx.x * 256 + threadIdx.x;  // 0..4095
    const int k  = blockIdx.y;                      // chunk
    const int b  = ch >> 10;
    const int hd = ch & 1023;
    const float* gp = g_gates + (size_t)b * 2048 * 4096 + (size_t)k * CHUNK * 4096 + hd;

    float m = -1e30f, c = 0.f, n = 0.f, F = 0.f;

#pragma unroll 8
    for (int s = 0; s < CHUNK; ++s) {
        const float* row = gp + (size_t)s * 4096;
        float zb = __ldg(row);
        float ib = __ldg(row + 1024);
        float fb = __ldg(row + 2048);

        float zv = 1.f - __fdividef(2.f, __expf(2.f * zb) + 1.f);

        float lf = fb, li = ib;
        if (fminf(fb, ib) < -6.f) {
            lf = __logf(__expf(fb) + EPSV);
            li = __logf(__expf(ib) + EPSV);
        }
        F += lf;

        float mn = fmaxf(lf + m, li);
        float ih = __expf(li - mn);
        float fh = __expf(lf + m - mn);
        c = fmaf(fh, c, ih * zv);
        n = fmaf(fh, n, ih);
        m = mn;
    }
    g_cstate[(size_t)k * NCH + ch] = make_float4(F, m, c, n);
}

// ===========================================================================
// Scan phase 2: sequential combine with batch-of-8 register prefetch.
// ===========================================================================
__global__ __launch_bounds__(256) void scan_combine_kernel(float* __restrict__ Out)
{
    const int ch = blockIdx.x * 256 + threadIdx.x;  // 0..4095
    float m = 0.f, c = 0.f, n = 0.f;

#pragma unroll 1
    for (int k0 = 0; k0 < NCHUNK; k0 += 8) {
        float4 buf[8];
#pragma unroll
        for (int j = 0; j < 8; ++j)
            buf[j] = g_cstate[(size_t)(k0 + j) * NCH + ch];
#pragma unroll
        for (int j = 0; j < 8; ++j) {
            g_carry[(size_t)(k0 + j) * NCH + ch] = make_float4(m, c, n, 0.f);
            float4 st = buf[j];  // (F, m_loc, c_loc, n_loc)
            float mo = fmaxf(st.x + m, st.y);
            float ea = __expf(st.x + m - mo);
            float eb = __expf(st.y - mo);
            c = fmaf(ea, c, eb * st.z);
            n = fmaf(ea, n, eb * st.w);
            m = mo;
        }
    }
    Out[8388608 + 4096 + ch]  = c;   // c_f
    Out[8388608 + 8192 + ch]  = n;   // n_f
    Out[8388608 + 12288 + ch] = m;   // m_f
}

// ===========================================================================
// Scan phase 3: replay each chunk from its exact carry-in and emit h.
// ===========================================================================
__global__ __launch_bounds__(256) void scan_emit_kernel(float* __restrict__ Out)
{
    const int ch = blockIdx.x * 256 + threadIdx.x;
    const int k  = blockIdx.y;
    const int b  = ch >> 10;
    const int hd = ch & 1023;
    const float* gp = g_gates + (size_t)b * 2048 * 4096 + (size_t)k * CHUNK * 4096 + hd;
    float* hp = Out + (size_t)b * 2048 * 1024 + (size_t)k * CHUNK * 1024 + hd;

    float4 cr = g_carry[(size_t)k * NCH + ch];
    float m = cr.x, c = cr.y, n = cr.z, hv = 0.f;

#pragma unroll 8
    for (int s = 0; s < CHUNK; ++s) {
        const float* row = gp + (size_t)s * 4096;
        float zb = __ldg(row);
        float ib = __ldg(row + 1024);
        float fb = __ldg(row + 2048);
        float ob = __ldg(row + 3072);

        float zv = 1.f - __fdividef(2.f, __expf(2.f * zb) + 1.f);
        float ov = __fdividef(1.f, 1.f + __expf(-ob));

        float lf = fb, li = ib;
        if (fminf(fb, ib) < -6.f) {
            lf = __logf(__expf(fb) + EPSV);
            li = __logf(__expf(ib) + EPSV);
        }

        float mn = fmaxf(lf + m, li);
        float ih = __expf(li - mn);
        float fh = __expf(lf + m - mn);
        c = fmaf(fh, c, ih * zv);
        n = fmaf(fh, n, ih);
        m = mn;
        hv = ov * __fdividef(c, n + EPSV);
        hp[(size_t)s * 1024] = hv;
    }

    if (k == NCHUNK - 1) Out[8388608 + ch] = hv;  // h_f
}

// ---------------------------------------------------------------------------
extern "C" void kernel_launch(void* const* d_in, const int* in_sizes, int n_in,
                              void* d_out, int out_size)
{
    const float* X  = (const float*)d_in[0];  // [4, 2048, 4096]
    const float* W  = (const float*)d_in[1];  // [4, 4, 256, 256]
    const float* Bv = (const float*)d_in[2];  // [4, 4, 256]
    float* out = (float*)d_out;

    cudaFuncSetAttribute(gemm_mma_kernel, cudaFuncAttributeMaxDynamicSharedMemorySize,
                         SMEM_GEMM);

    wsplit_kernel<<<1024, 256>>>(W);
    gemm_mma_kernel<<<dim3(64, 16), 512, SMEM_GEMM>>>(X, Bv);
    scan_local_kernel<<<dim3(16, NCHUNK), 256>>>();
    scan_combine_kernel<<<16, 256>>>(out);
    scan_emit_kernel<<<dim3(16, NCHUNK), 256>>>(out);
}

// round 14
// speedup vs baseline: 1.4970x; 1.0394x over previous
#include <cuda_runtime.h>
#include <cuda_fp16.h>
#include <cstdint>
#include <cstddef>

#define EPSV 1e-8f
#define CHUNK 64
#define NCHUNK 32
#define NCH 4096  // channels = B*NH*HD

// Gate pre-activations scratch: [B=4][S=2048][4 gates][NH=4][HD=256] fp32 = 128 MiB
static __device__ float g_gates[33554432];
// per-(chunk,channel) local state (F, m_loc, c_loc, n_loc)
static __device__ float4 g_cstate[NCHUNK * NCH];
// per-(chunk,channel) carry-in state (m, c, n, -)
static __device__ float4 g_carry[NCHUNK * NCH];
// Pre-split weights: fp16 hi/lo, layout [gh][n][k] like W
static __device__ __half g_W0[1048576];
static __device__ __half g_W1[1048576];

// ---------------------------------------------------------------------------
__device__ __forceinline__ uint32_t smem_u32(const void* p) {
    uint32_t a;
    asm("{ .reg .u64 t; cvta.to.shared.u64 t, %1; cvt.u32.u64 %0, t; }" : "=r"(a) : "l"(p));
    return a;
}
__device__ __forceinline__ void ldsm4(uint32_t* r, uint32_t addr) {
    asm volatile("ldmatrix.sync.aligned.m8n8.x4.shared.b16 {%0,%1,%2,%3}, [%4];"
                 : "=r"(r[0]), "=r"(r[1]), "=r"(r[2]), "=r"(r[3]) : "r"(addr));
}
__device__ __forceinline__ void mma16816(float* c, const uint32_t* a, const uint32_t* b) {
    asm volatile(
        "mma.sync.aligned.m16n8k16.row.col.f32.f16.f16.f32 "
        "{%0,%1,%2,%3}, {%4,%5,%6,%7}, {%8,%9}, {%0,%1,%2,%3};"
        : "+f"(c[0]), "+f"(c[1]), "+f"(c[2]), "+f"(c[3])
        : "r"(a[0]), "r"(a[1]), "r"(a[2]), "r"(a[3]), "r"(b[0]), "r"(b[1]));
}
#define CP_ASYNC16(sa, gp) \
    asm volatile("cp.async.ca.shared.global [%0], [%1], 16;" :: "r"(sa), "l"(gp))
#define CP_COMMIT() asm volatile("cp.async.commit_group;" ::: "memory")
#define CP_WAIT0()  asm volatile("cp.async.wait_group 0;" ::: "memory")

// convert 8 fp32 -> fp16 hi (uint2 x2) + lo (uint2 x2)
__device__ __forceinline__ void split8(const float4& v0, const float4& v1,
                                       uint2& h_a, uint2& h_b, uint2& l_a, uint2& l_b) {
    __half2 h0 = __floats2half2_rn(v0.x, v0.y);
    __half2 h1 = __floats2half2_rn(v0.z, v0.w);
    __half2 h2 = __floats2half2_rn(v1.x, v1.y);
    __half2 h3 = __floats2half2_rn(v1.z, v1.w);
    float2 f0 = __half22float2(h0), f1 = __half22float2(h1);
    float2 f2 = __half22float2(h2), f3 = __half22float2(h3);
    __half2 l0 = __floats2half2_rn(v0.x - f0.x, v0.y - f0.y);
    __half2 l1 = __floats2half2_rn(v0.z - f1.x, v0.w - f1.y);
    __half2 l2 = __floats2half2_rn(v1.x - f2.x, v1.y - f2.y);
    __half2 l3 = __floats2half2_rn(v1.z - f3.x, v1.w - f3.y);
    h_a.x = *(const uint32_t*)&h0; h_a.y = *(const uint32_t*)&h1;
    h_b.x = *(const uint32_t*)&h2; h_b.y = *(const uint32_t*)&h3;
    l_a.x = *(const uint32_t*)&l0; l_a.y = *(const uint32_t*)&l1;
    l_b.x = *(const uint32_t*)&l2; l_b.y = *(const uint32_t*)&l3;
}
// hi-only convert
__device__ __forceinline__ void hi8(const float4& v0, const float4& v1,
                                    uint2& h_a, uint2& h_b) {
    __half2 h0 = __floats2half2_rn(v0.x, v0.y);
    __half2 h1 = __floats2half2_rn(v0.z, v0.w);
    __half2 h2 = __floats2half2_rn(v1.x, v1.y);
    __half2 h3 = __floats2half2_rn(v1.z, v1.w);
    h_a.x = *(const uint32_t*)&h0; h_a.y = *(const uint32_t*)&h1;
    h_b.x = *(const uint32_t*)&h2; h_b.y = *(const uint32_t*)&h3;
}

// ===========================================================================
// Kernel 0: pre-split W (fp32 -> fp16 hi + fp16 lo). 1,048,576 elements.
// ===========================================================================
__global__ __launch_bounds__(256) void wsplit_kernel(const float* __restrict__ W)
{
    const int i = blockIdx.x * 256 + threadIdx.x;  // float4 id, 262144 total
    float4 v = *(const float4*)(W + (size_t)i * 4);
    __half2 h0 = __floats2half2_rn(v.x, v.y);
    __half2 h1 = __floats2half2_rn(v.z, v.w);
    float2 f0 = __half22float2(h0), f1 = __half22float2(h1);
    __half2 l0 = __floats2half2_rn(v.x - f0.x, v.y - f0.y);
    __half2 l1 = __floats2half2_rn(v.z - f1.x, v.w - f1.y);
    uint2 ha, la;
    ha.x = *(const uint32_t*)&h0; ha.y = *(const uint32_t*)&h1;
    la.x = *(const uint32_t*)&l0; la.y = *(const uint32_t*)&l1;
    *(uint2*)&g_W0[(size_t)i * 4] = ha;
    *(uint2*)&g_W1[(size_t)i * 4] = la;
}

// ===========================================================================
// Kernel 1: block-diagonal GEMM via mma.sync fp16.
//   Per-gate precision: f gate (g==2) 3-term 2-split; z,i,o single-term fp16.
//   Gate in blockIdx.x LSBs -> heavy f blocks interleave evenly across waves.
//   grid (256 = 64 m-tiles x 4 g, 4 h), 512 threads = 16 warps (2 m x 8 n),
//   warp tile 64x32. K=256, 8 chunks of 32.
//   A: LDG->convert->STS double-buffered. B: cp.async double-buffered.
//   smem rows: 32 fp16 (64B) + 16B pad = 80B pitch (conflict-free ldmatrix).
// ===========================================================================
#define APITCH 80
#define SA0 0            // 128 rows * 80B = 10240
#define SA1 10240
#define SB0 20480        // 256 rows * 80B = 20480
#define SB1 40960
#define BUFSZ 61440
#define SMEM_GEMM (2 * BUFSZ)

__global__ __launch_bounds__(512) void gemm_mma_kernel(
    const float* __restrict__ X, const float* __restrict__ Bias)
{
    extern __shared__ __align__(16) char smem[];
    const uint32_t sb = smem_u32(smem);

    const int tid  = threadIdx.x;
    const int lane = tid & 31;
    const int wid  = tid >> 5;
    const int wm   = (wid & 1) * 64;   // warp m offset
    const int wn   = (wid >> 1) * 32;  // warp n offset
    const int bx   = blockIdx.x >> 2;  // m tile
    const int g    = blockIdx.x & 3;   // gate (fastest in bid order)
    const int hh   = blockIdx.y;       // head
    const int ghm  = g * 4 + hh;       // 256-col block index: g*1024 + hh*256
    const bool full = (g == 2);        // f gate: 3-term split

    float c[4][4][4];
#pragma unroll
    for (int i = 0; i < 4; ++i)
#pragma unroll
        for (int j = 0; j < 4; ++j)
#pragma unroll
            for (int q = 0; q < 4; ++q) c[i][j][q] = 0.f;

    // ---- staging assignments ----
    const float* xp = X + (size_t)(bx * 128 + (tid >> 2)) * 4096 + ghm * 256 + (tid & 3) * 8;
    const uint32_t aSt0 = (uint32_t)(tid >> 2) * APITCH + (tid & 3) * 16;
    const __half* w0p = g_W0 + (size_t)ghm * 65536 + (size_t)(tid >> 1) * 256 + (tid & 1) * 16;
    const __half* w1p = g_W1 + (size_t)ghm * 65536 + (size_t)(tid >> 1) * 256 + (tid & 1) * 16;
    const uint32_t bSt = (uint32_t)(tid >> 1) * APITCH + (tid & 1) * 32;

    // ldmatrix base offsets (within a buffer)
    const uint32_t aRowOff = SA0 + (uint32_t)(wm + (lane & 15)) * APITCH + (lane >> 4) * 16;
    const uint32_t bRowOff = SB0 + (uint32_t)(wn + (lane & 7) + (lane >> 4) * 8) * APITCH
                           + ((lane >> 3) & 1) * 16;

    // ---- prologue: stage chunk 0 into buffer 0 ----
    {
        float4 v0 = *(const float4*)xp;
        float4 v1 = *(const float4*)(xp + 4);
        if (full) {
            uint2 ha, hb, la, lb;
            split8(v0, v1, ha, hb, la, lb);
            *(uint2*)(smem + SA0 + aSt0) = ha;
            *(uint2*)(smem + SA0 + aSt0 + 8) = hb;
            *(uint2*)(smem + SA1 + aSt0) = la;
            *(uint2*)(smem + SA1 + aSt0 + 8) = lb;
            CP_ASYNC16(sb + SB1 + bSt,      w1p);
            CP_ASYNC16(sb + SB1 + bSt + 16, w1p + 8);
        } else {
            uint2 ha, hb;
            hi8(v0, v1, ha, hb);
            *(uint2*)(smem + SA0 + aSt0) = ha;
            *(uint2*)(smem + SA0 + aSt0 + 8) = hb;
        }
        CP_ASYNC16(sb + SB0 + bSt,      w0p);
        CP_ASYNC16(sb + SB0 + bSt + 16, w0p + 8);
        CP_COMMIT();
    }
    CP_WAIT0();
    __syncthreads();

#pragma unroll 1
    for (int ck = 0; ck < 8; ++ck) {
        const uint32_t bufS = (uint32_t)(ck & 1) * BUFSZ;
        const uint32_t bufN = (uint32_t)((ck + 1) & 1) * BUFSZ;

        float4 v0, v1;
        if (ck < 7) {
            v0 = *(const float4*)(xp + (ck + 1) * 32);
            v1 = *(const float4*)(xp + (ck + 1) * 32 + 4);
            CP_ASYNC16(sb + bufN + SB0 + bSt,      w0p + (ck + 1) * 32);
            CP_ASYNC16(sb + bufN + SB0 + bSt + 16, w0p + (ck + 1) * 32 + 8);
            if (full) {
                CP_ASYNC16(sb + bufN + SB1 + bSt,      w1p + (ck + 1) * 32);
                CP_ASYNC16(sb + bufN + SB1 + bSt + 16, w1p + (ck + 1) * 32 + 8);
            }
            CP_COMMIT();
        }

        // ---- MMA phase: 2 k16 subchunks; f gate adds 2 correction terms ----
        const uint32_t aRow = sb + bufS + aRowOff;
        const uint32_t bRow = sb + bufS + bRowOff;
#pragma unroll
        for (int s = 0; s < 2; ++s) {
            const uint32_t acol = (uint32_t)s * 32;
            uint32_t a[4][4], b[2][4];
            // A0 + B0 frags, main term
#pragma unroll
            for (int mf = 0; mf < 4; ++mf) ldsm4(a[mf], aRow + acol + mf * 16 * APITCH);
#pragma unroll
            for (int p = 0; p < 2; ++p) ldsm4(b[p], bRow + acol + p * 16 * APITCH);
#pragma unroll
            for (int mf = 0; mf < 4; ++mf)
#pragma unroll
                for (int p = 0; p < 2; ++p) {
                    mma16816(c[mf][p * 2],     a[mf], &b[p][0]);
                    mma16816(c[mf][p * 2 + 1], a[mf], &b[p][2]);
                }
            if (full) {
                // term A0*B1
#pragma unroll
                for (int p = 0; p < 2; ++p) ldsm4(b[p], bRow + (SB1 - SB0) + acol + p * 16 * APITCH);
#pragma unroll
                for (int mf = 0; mf < 4; ++mf)
#pragma unroll
                    for (int p = 0; p < 2; ++p) {
                        mma16816(c[mf][p * 2],     a[mf], &b[p][0]);
                        mma16816(c[mf][p * 2 + 1], a[mf], &b[p][2]);
                    }
                // term A1*B0
#pragma unroll
                for (int mf = 0; mf < 4; ++mf) ldsm4(a[mf], aRow + (SA1 - SA0) + acol + mf * 16 * APITCH);
#pragma unroll
                for (int p = 0; p < 2; ++p) ldsm4(b[p], bRow + acol + p * 16 * APITCH);
#pragma unroll
                for (int mf = 0; mf < 4; ++mf)
#pragma unroll
                    for (int p = 0; p < 2; ++p) {
                        mma16816(c[mf][p * 2],     a[mf], &b[p][0]);
                        mma16816(c[mf][p * 2 + 1], a[mf], &b[p][2]);
                    }
            }
        }

        // ---- stage A for next chunk into next buffer ----
        if (ck < 7) {
            if (full) {
                uint2 ha, hb, la, lb;
                split8(v0, v1, ha, hb, la, lb);
                *(uint2*)(smem + bufN + SA0 + aSt0) = ha;
                *(uint2*)(smem + bufN + SA0 + aSt0 + 8) = hb;
                *(uint2*)(smem + bufN + SA1 + aSt0) = la;
                *(uint2*)(smem + bufN + SA1 + aSt0 + 8) = lb;
            } else {
                uint2 ha, hb;
                hi8(v0, v1, ha, hb);
                *(uint2*)(smem + bufN + SA0 + aSt0) = ha;
                *(uint2*)(smem + bufN + SA0 + aSt0 + 8) = hb;
            }
        }
        CP_WAIT0();
        __syncthreads();
    }

    // ---- epilogue: bias + store ----
    const float* bp = Bias + ghm * 256 + wn + (lane & 3) * 2;
    const int mbase = bx * 128 + wm + (lane >> 2);
    float* gbase = g_gates + (size_t)mbase * 4096 + ghm * 256 + wn + (lane & 3) * 2;

#pragma unroll
    for (int nf = 0; nf < 4; ++nf) {
        float2 bv = *(const float2*)(bp + nf * 8);
#pragma unroll
        for (int mf = 0; mf < 4; ++mf) {
            float* p0 = gbase + (size_t)(mf * 16) * 4096 + nf * 8;
            float2 w0 = make_float2(c[mf][nf][0] + bv.x, c[mf][nf][1] + bv.y);
            float2 w1 = make_float2(c[mf][nf][2] + bv.x, c[mf][nf][3] + bv.y);
            *(float2*)p0 = w0;
            *(float2*)(p0 + 8 * 4096) = w1;
        }
    }
}

// ===========================================================================
// Scan phase 1: per-(channel, chunk) local reduction, batch-of-8 loads
// (explicit MLP so the serial scan chain doesn't throttle memory).
// ===========================================================================
__global__ __launch_bounds__(256) void scan_local_kernel()
{
    const int ch = blockIdx.x * 256 + threadIdx.x;  // 0..4095
    const int k  = blockIdx.y;                      // chunk
    const int b  = ch >> 10;
    const int hd = ch & 1023;
    const float* gp = g_gates + (size_t)b * 2048 * 4096 + (size_t)k * CHUNK * 4096 + hd;

    float m = -1e30f, c = 0.f, n = 0.f, F = 0.f;

#pragma unroll 1
    for (int s0 = 0; s0 < CHUNK; s0 += 8) {
        float zb[8], ib[8], fb[8];
#pragma unroll
        for (int j = 0; j < 8; ++j) {
            const float* row = gp + (size_t)(s0 + j) * 4096;
            zb[j] = __ldg(row);
            ib[j] = __ldg(row + 1024);
            fb[j] = __ldg(row + 2048);
        }
#pragma unroll
        for (int j = 0; j < 8; ++j) {
            float zv = 1.f - __fdividef(2.f, __expf(2.f * zb[j]) + 1.f);
            float lf = fb[j], li = ib[j];
            if (fminf(fb[j], ib[j]) < -6.f) {
                lf = __logf(__expf(fb[j]) + EPSV);
                li = __logf(__expf(ib[j]) + EPSV);
            }
            F += lf;
            float mn = fmaxf(lf + m, li);
            float ih = __expf(li - mn);
            float fh = __expf(lf + m - mn);
            c = fmaf(fh, c, ih * zv);
            n = fmaf(fh, n, ih);
            m = mn;
        }
    }
    g_cstate[(size_t)k * NCH + ch] = make_float4(F, m, c, n);
}

// ===========================================================================
// Scan phase 2: sequential combine with batch-of-8 register prefetch.
// ===========================================================================
__global__ __launch_bounds__(256) void scan_combine_kernel(float* __restrict__ Out)
{
    const int ch = blockIdx.x * 256 + threadIdx.x;  // 0..4095
    float m = 0.f, c = 0.f, n = 0.f;

#pragma unroll 1
    for (int k0 = 0; k0 < NCHUNK; k0 += 8) {
        float4 buf[8];
#pragma unroll
        for (int j = 0; j < 8; ++j)
            buf[j] = g_cstate[(size_t)(k0 + j) * NCH + ch];
#pragma unroll
        for (int j = 0; j < 8; ++j) {
            g_carry[(size_t)(k0 + j) * NCH + ch] = make_float4(m, c, n, 0.f);
            float4 st = buf[j];  // (F, m_loc, c_loc, n_loc)
            float mo = fmaxf(st.x + m, st.y);
            float ea = __expf(st.x + m - mo);
            float eb = __expf(st.y - mo);
            c = fmaf(ea, c, eb * st.z);
            n = fmaf(ea, n, eb * st.w);
            m = mo;
        }
    }
    Out[8388608 + 4096 + ch]  = c;   // c_f
    Out[8388608 + 8192 + ch]  = n;   // n_f
    Out[8388608 + 12288 + ch] = m;   // m_f
}

// ===========================================================================
// Scan phase 3: replay each chunk from its exact carry-in, batch-of-8 loads.
// ===========================================================================
__global__ __launch_bounds__(256) void scan_emit_kernel(float* __restrict__ Out)
{
    const int ch = blockIdx.x * 256 + threadIdx.x;
    const int k  = blockIdx.y;
    const int b  = ch >> 10;
    const int hd = ch & 1023;
    const float* gp = g_gates + (size_t)b * 2048 * 4096 + (size_t)k * CHUNK * 4096 + hd;
    float* hp = Out + (size_t)b * 2048 * 1024 + (size_t)k * CHUNK * 1024 + hd;

    float4 cr = g_carry[(size_t)k * NCH + ch];
    float m = cr.x, c = cr.y, n = cr.z, hv = 0.f;

#pragma unroll 1
    for (int s0 = 0; s0 < CHUNK; s0 += 8) {
        float zb[8], ib[8], fb[8], ob[8];
#pragma unroll
        for (int j = 0; j < 8; ++j) {
            const float* row = gp + (size_t)(s0 + j) * 4096;
            zb[j] = __ldg(row);
            ib[j] = __ldg(row + 1024);
            fb[j] = __ldg(row + 2048);
            ob[j] = __ldg(row + 3072);
        }
#pragma unroll
        for (int j = 0; j < 8; ++j) {
            float zv = 1.f - __fdividef(2.f, __expf(2.f * zb[j]) + 1.f);
            float ov = __fdividef(1.f, 1.f + __expf(-ob[j]));
            float lf = fb[j], li = ib[j];
            if (fminf(fb[j], ib[j]) < -6.f) {
                lf = __logf(__expf(fb[j]) + EPSV);
                li = __logf(__expf(ib[j]) + EPSV);
            }
            float mn = fmaxf(lf + m, li);
            float ih = __expf(li - mn);
            float fh = __expf(lf + m - mn);
            c = fmaf(fh, c, ih * zv);
            n = fmaf(fh, n, ih);
            m = mn;
            hv = ov * __fdividef(c, n + EPSV);
            hp[(size_t)(s0 + j) * 1024] = hv;
        }
    }

    if (k == NCHUNK - 1) Out[8388608 + ch] = hv;  // h_f
}

// ---------------------------------------------------------------------------
extern "C" void kernel_launch(void* const* d_in, const int* in_sizes, int n_in,
                              void* d_out, int out_size)
{
    const float* X  = (const float*)d_in[0];  // [4, 2048, 4096]
    const float* W  = (const float*)d_in[1];  // [4, 4, 256, 256]
    const float* Bv = (const float*)d_in[2];  // [4, 4, 256]
    float* out = (float*)d_out;

    cudaFuncSetAttribute(gemm_mma_kernel, cudaFuncAttributeMaxDynamicSharedMemorySize,
                         SMEM_GEMM);

    wsplit_kernel<<<1024, 256>>>(W);
    gemm_mma_kernel<<<dim3(256, 4), 512, SMEM_GEMM>>>(X, Bv);
    scan_local_kernel<<<dim3(16, NCHUNK), 256>>>();
    scan_combine_kernel<<<16, 256>>>(out);
    scan_emit_kernel<<<dim3(16, NCHUNK), 256>>>(out);
}

// round 15
// speedup vs baseline: 1.5472x; 1.0336x over previous
#include <cuda_runtime.h>
#include <cuda_fp16.h>
#include <cstdint>
#include <cstddef>

#define EPSV 1e-8f
#define CHUNK 64
#define NCHUNK 32
#define NCH 4096  // channels = B*NH*HD

// Gate pre-activations, per-gate arrays [m=B*S][NH*HD=1024]:
//   f fp32 (precision-critical), z/i/o fp16 (single-shot errors only)
static __device__ float  g_gf[8388608];   // 32 MB
static __device__ __half g_gz[8388608];   // 16 MB
static __device__ __half g_gi[8388608];   // 16 MB
static __device__ __half g_go[8388608];   // 16 MB
// per-(chunk,channel) local state (F, m_loc, c_loc, n_loc)
static __device__ float4 g_cstate[NCHUNK * NCH];
// per-(chunk,channel) carry-in state (m, c, n, -)
static __device__ float4 g_carry[NCHUNK * NCH];
// Pre-split weights: fp16 hi/lo, layout [gh][n][k] like W
static __device__ __half g_W0[1048576];
static __device__ __half g_W1[1048576];

// ---------------------------------------------------------------------------
__device__ __forceinline__ uint32_t smem_u32(const void* p) {
    uint32_t a;
    asm("{ .reg .u64 t; cvta.to.shared.u64 t, %1; cvt.u32.u64 %0, t; }" : "=r"(a) : "l"(p));
    return a;
}
__device__ __forceinline__ void ldsm4(uint32_t* r, uint32_t addr) {
    asm volatile("ldmatrix.sync.aligned.m8n8.x4.shared.b16 {%0,%1,%2,%3}, [%4];"
                 : "=r"(r[0]), "=r"(r[1]), "=r"(r[2]), "=r"(r[3]) : "r"(addr));
}
__device__ __forceinline__ void mma16816(float* c, const uint32_t* a, const uint32_t* b) {
    asm volatile(
        "mma.sync.aligned.m16n8k16.row.col.f32.f16.f16.f32 "
        "{%0,%1,%2,%3}, {%4,%5,%6,%7}, {%8,%9}, {%0,%1,%2,%3};"
        : "+f"(c[0]), "+f"(c[1]), "+f"(c[2]), "+f"(c[3])
        : "r"(a[0]), "r"(a[1]), "r"(a[2]), "r"(a[3]), "r"(b[0]), "r"(b[1]));
}
#define CP_ASYNC16(sa, gp) \
    asm volatile("cp.async.ca.shared.global [%0], [%1], 16;" :: "r"(sa), "l"(gp))
#define CP_COMMIT() asm volatile("cp.async.commit_group;" ::: "memory")
#define CP_WAIT0()  asm volatile("cp.async.wait_group 0;" ::: "memory")

// convert 8 fp32 -> fp16 hi (uint2 x2) + lo (uint2 x2)
__device__ __forceinline__ void split8(const float4& v0, const float4& v1,
                                       uint2& h_a, uint2& h_b, uint2& l_a, uint2& l_b) {
    __half2 h0 = __floats2half2_rn(v0.x, v0.y);
    __half2 h1 = __floats2half2_rn(v0.z, v0.w);
    __half2 h2 = __floats2half2_rn(v1.x, v1.y);
    __half2 h3 = __floats2half2_rn(v1.z, v1.w);
    float2 f0 = __half22float2(h0), f1 = __half22float2(h1);
    float2 f2 = __half22float2(h2), f3 = __half22float2(h3);
    __half2 l0 = __floats2half2_rn(v0.x - f0.x, v0.y - f0.y);
    __half2 l1 = __floats2half2_rn(v0.z - f1.x, v0.w - f1.y);
    __half2 l2 = __floats2half2_rn(v1.x - f2.x, v1.y - f2.y);
    __half2 l3 = __floats2half2_rn(v1.z - f3.x, v1.w - f3.y);
    h_a.x = *(const uint32_t*)&h0; h_a.y = *(const uint32_t*)&h1;
    h_b.x = *(const uint32_t*)&h2; h_b.y = *(const uint32_t*)&h3;
    l_a.x = *(const uint32_t*)&l0; l_a.y = *(const uint32_t*)&l1;
    l_b.x = *(const uint32_t*)&l2; l_b.y = *(const uint32_t*)&l3;
}
// hi-only convert
__device__ __forceinline__ void hi8(const float4& v0, const float4& v1,
                                    uint2& h_a, uint2& h_b) {
    __half2 h0 = __floats2half2_rn(v0.x, v0.y);
    __half2 h1 = __floats2half2_rn(v0.z, v0.w);
    __half2 h2 = __floats2half2_rn(v1.x, v1.y);
    __half2 h3 = __floats2half2_rn(v1.z, v1.w);
    h_a.x = *(const uint32_t*)&h0; h_a.y = *(const uint32_t*)&h1;
    h_b.x = *(const uint32_t*)&h2; h_b.y = *(const uint32_t*)&h3;
}

// ===========================================================================
// Kernel 0: pre-split W (fp32 -> fp16 hi + fp16 lo). 1,048,576 elements.
// ===========================================================================
__global__ __launch_bounds__(256) void wsplit_kernel(const float* __restrict__ W)
{
    const int i = blockIdx.x * 256 + threadIdx.x;  // float4 id, 262144 total
    float4 v = *(const float4*)(W + (size_t)i * 4);
    __half2 h0 = __floats2half2_rn(v.x, v.y);
    __half2 h1 = __floats2half2_rn(v.z, v.w);
    float2 f0 = __half22float2(h0), f1 = __half22float2(h1);
    __half2 l0 = __floats2half2_rn(v.x - f0.x, v.y - f0.y);
    __half2 l1 = __floats2half2_rn(v.z - f1.x, v.w - f1.y);
    uint2 ha, la;
    ha.x = *(const uint32_t*)&h0; ha.y = *(const uint32_t*)&h1;
    la.x = *(const uint32_t*)&l0; la.y = *(const uint32_t*)&l1;
    *(uint2*)&g_W0[(size_t)i * 4] = ha;
    *(uint2*)&g_W1[(size_t)i * 4] = la;
}

// ===========================================================================
// Kernel 1: block-diagonal GEMM via mma.sync fp16.
//   Per-gate precision: f gate (g==2) 3-term 2-split, fp32 output;
//   z,i,o single-term fp16, fp16 output (halves gate-store traffic).
//   Gate in blockIdx.x LSBs -> heavy f blocks interleave evenly across waves.
//   grid (256 = 64 m-tiles x 4 g, 4 h), 512 threads = 16 warps (2 m x 8 n),
//   warp tile 64x32. K=256, 8 chunks of 32.
// ===========================================================================
#define APITCH 80
#define SA0 0            // 128 rows * 80B = 10240
#define SA1 10240
#define SB0 20480        // 256 rows * 80B = 20480
#define SB1 40960
#define BUFSZ 61440
#define SMEM_GEMM (2 * BUFSZ)

__global__ __launch_bounds__(512) void gemm_mma_kernel(
    const float* __restrict__ X, const float* __restrict__ Bias)
{
    extern __shared__ __align__(16) char smem[];
    const uint32_t sb = smem_u32(smem);

    const int tid  = threadIdx.x;
    const int lane = tid & 31;
    const int wid  = tid >> 5;
    const int wm   = (wid & 1) * 64;   // warp m offset
    const int wn   = (wid >> 1) * 32;  // warp n offset
    const int bx   = blockIdx.x >> 2;  // m tile
    const int g    = blockIdx.x & 3;   // gate (fastest in bid order)
    const int hh   = blockIdx.y;       // head
    const int ghm  = g * 4 + hh;       // 256-col block index in X / W
    const bool full = (g == 2);        // f gate: 3-term split

    float c[4][4][4];
#pragma unroll
    for (int i = 0; i < 4; ++i)
#pragma unroll
        for (int j = 0; j < 4; ++j)
#pragma unroll
            for (int q = 0; q < 4; ++q) c[i][j][q] = 0.f;

    // ---- staging assignments ----
    const float* xp = X + (size_t)(bx * 128 + (tid >> 2)) * 4096 + ghm * 256 + (tid & 3) * 8;
    const uint32_t aSt0 = (uint32_t)(tid >> 2) * APITCH + (tid & 3) * 16;
    const __half* w0p = g_W0 + (size_t)ghm * 65536 + (size_t)(tid >> 1) * 256 + (tid & 1) * 16;
    const __half* w1p = g_W1 + (size_t)ghm * 65536 + (size_t)(tid >> 1) * 256 + (tid & 1) * 16;
    const uint32_t bSt = (uint32_t)(tid >> 1) * APITCH + (tid & 1) * 32;

    // ldmatrix base offsets (within a buffer)
    const uint32_t aRowOff = SA0 + (uint32_t)(wm + (lane & 15)) * APITCH + (lane >> 4) * 16;
    const uint32_t bRowOff = SB0 + (uint32_t)(wn + (lane & 7) + (lane >> 4) * 8) * APITCH
                           + ((lane >> 3) & 1) * 16;

    // ---- prologue: stage chunk 0 into buffer 0 ----
    {
        float4 v0 = *(const float4*)xp;
        float4 v1 = *(const float4*)(xp + 4);
        if (full) {
            uint2 ha, hb, la, lb;
            split8(v0, v1, ha, hb, la, lb);
            *(uint2*)(smem + SA0 + aSt0) = ha;
            *(uint2*)(smem + SA0 + aSt0 + 8) = hb;
            *(uint2*)(smem + SA1 + aSt0) = la;
            *(uint2*)(smem + SA1 + aSt0 + 8) = lb;
            CP_ASYNC16(sb + SB1 + bSt,      w1p);
            CP_ASYNC16(sb + SB1 + bSt + 16, w1p + 8);
        } else {
            uint2 ha, hb;
            hi8(v0, v1, ha, hb);
            *(uint2*)(smem + SA0 + aSt0) = ha;
            *(uint2*)(smem + SA0 + aSt0 + 8) = hb;
        }
        CP_ASYNC16(sb + SB0 + bSt,      w0p);
        CP_ASYNC16(sb + SB0 + bSt + 16, w0p + 8);
        CP_COMMIT();
    }
    CP_WAIT0();
    __syncthreads();

#pragma unroll 1
    for (int ck = 0; ck < 8; ++ck) {
        const uint32_t bufS = (uint32_t)(ck & 1) * BUFSZ;
        const uint32_t bufN = (uint32_t)((ck + 1) & 1) * BUFSZ;

        float4 v0, v1;
        if (ck < 7) {
            v0 = *(const float4*)(xp + (ck + 1) * 32);
            v1 = *(const float4*)(xp + (ck + 1) * 32 + 4);
            CP_ASYNC16(sb + bufN + SB0 + bSt,      w0p + (ck + 1) * 32);
            CP_ASYNC16(sb + bufN + SB0 + bSt + 16, w0p + (ck + 1) * 32 + 8);
            if (full) {
                CP_ASYNC16(sb + bufN + SB1 + bSt,      w1p + (ck + 1) * 32);
                CP_ASYNC16(sb + bufN + SB1 + bSt + 16, w1p + (ck + 1) * 32 + 8);
            }
            CP_COMMIT();
        }

        // ---- MMA phase: 2 k16 subchunks; f gate adds 2 correction terms ----
        const uint32_t aRow = sb + bufS + aRowOff;
        const uint32_t bRow = sb + bufS + bRowOff;
#pragma unroll
        for (int s = 0; s < 2; ++s) {
            const uint32_t acol = (uint32_t)s * 32;
            uint32_t a[4][4], b[2][4];
#pragma unroll
            for (int mf = 0; mf < 4; ++mf) ldsm4(a[mf], aRow + acol + mf * 16 * APITCH);
#pragma unroll
            for (int p = 0; p < 2; ++p) ldsm4(b[p], bRow + acol + p * 16 * APITCH);
#pragma unroll
            for (int mf = 0; mf < 4; ++mf)
#pragma unroll
                for (int p = 0; p < 2; ++p) {
                    mma16816(c[mf][p * 2],     a[mf], &b[p][0]);
                    mma16816(c[mf][p * 2 + 1], a[mf], &b[p][2]);
                }
            if (full) {
                // term A0*B1
#pragma unroll
                for (int p = 0; p < 2; ++p) ldsm4(b[p], bRow + (SB1 - SB0) + acol + p * 16 * APITCH);
#pragma unroll
                for (int mf = 0; mf < 4; ++mf)
#pragma unroll
                    for (int p = 0; p < 2; ++p) {
                        mma16816(c[mf][p * 2],     a[mf], &b[p][0]);
                        mma16816(c[mf][p * 2 + 1], a[mf], &b[p][2]);
                    }
                // term A1*B0
#pragma unroll
                for (int mf = 0; mf < 4; ++mf) ldsm4(a[mf], aRow + (SA1 - SA0) + acol + mf * 16 * APITCH);
#pragma unroll
                for (int p = 0; p < 2; ++p) ldsm4(b[p], bRow + acol + p * 16 * APITCH);
#pragma unroll
                for (int mf = 0; mf < 4; ++mf)
#pragma unroll
                    for (int p = 0; p < 2; ++p) {
                        mma16816(c[mf][p * 2],     a[mf], &b[p][0]);
                        mma16816(c[mf][p * 2 + 1], a[mf], &b[p][2]);
                    }
            }
        }

        // ---- stage A for next chunk into next buffer ----
        if (ck < 7) {
            if (full) {
                uint2 ha, hb, la, lb;
                split8(v0, v1, ha, hb, la, lb);
                *(uint2*)(smem + bufN + SA0 + aSt0) = ha;
                *(uint2*)(smem + bufN + SA0 + aSt0 + 8) = hb;
                *(uint2*)(smem + bufN + SA1 + aSt0) = la;
                *(uint2*)(smem + bufN + SA1 + aSt0 + 8) = lb;
            } else {
                uint2 ha, hb;
                hi8(v0, v1, ha, hb);
                *(uint2*)(smem + bufN + SA0 + aSt0) = ha;
                *(uint2*)(smem + bufN + SA0 + aSt0 + 8) = hb;
            }
        }
        CP_WAIT0();
        __syncthreads();
    }

    // ---- epilogue: bias + store (f -> fp32, z/i/o -> fp16) ----
    const int col = hh * 256 + wn + (lane & 3) * 2;   // within 1024
    const float* bp = Bias + ghm * 256 + wn + (lane & 3) * 2;
    const int mbase = bx * 128 + wm + (lane >> 2);

    if (full) {
        float* gbase = g_gf + (size_t)mbase * 1024 + col;
#pragma unroll
        for (int nf = 0; nf < 4; ++nf) {
            float2 bv = *(const float2*)(bp + nf * 8);
#pragma unroll
            for (int mf = 0; mf < 4; ++mf) {
                float* p0 = gbase + (size_t)(mf * 16) * 1024 + nf * 8;
                float2 w0 = make_float2(c[mf][nf][0] + bv.x, c[mf][nf][1] + bv.y);
                float2 w1 = make_float2(c[mf][nf][2] + bv.x, c[mf][nf][3] + bv.y);
                *(float2*)p0 = w0;
                *(float2*)(p0 + 8 * 1024) = w1;
            }
        }
    } else {
        __half* dst = (g == 0) ? g_gz : ((g == 1) ? g_gi : g_go);
        __half* gbase = dst + (size_t)mbase * 1024 + col;
#pragma unroll
        for (int nf = 0; nf < 4; ++nf) {
            float2 bv = *(const float2*)(bp + nf * 8);
#pragma unroll
            for (int mf = 0; mf < 4; ++mf) {
                __half* p0 = gbase + (size_t)(mf * 16) * 1024 + nf * 8;
                __half2 w0 = __floats2half2_rn(c[mf][nf][0] + bv.x, c[mf][nf][1] + bv.y);
                __half2 w1 = __floats2half2_rn(c[mf][nf][2] + bv.x, c[mf][nf][3] + bv.y);
                *(__half2*)p0 = w0;
                *(__half2*)(p0 + 8 * 1024) = w1;
            }
        }
    }
}

// ===========================================================================
// Scan phase 1: per-(channel, chunk) local reduction, batch-of-8 loads.
// ===========================================================================
__global__ __launch_bounds__(256) void scan_local_kernel()
{
    const int ch = blockIdx.x * 256 + threadIdx.x;  // 0..4095
    const int k  = blockIdx.y;                      // chunk
    const int b  = ch >> 10;
    const int hd = ch & 1023;
    const size_t rb = (size_t)(b * 2048 + k * CHUNK) * 1024 + hd;
    const __half* zp = g_gz + rb;
    const __half* ip = g_gi + rb;
    const float*  fp = g_gf + rb;

    float m = -1e30f, c = 0.f, n = 0.f, F = 0.f;

#pragma unroll 1
    for (int s0 = 0; s0 < CHUNK; s0 += 8) {
        float zb[8], ib[8], fb[8];
#pragma unroll
        for (int j = 0; j < 8; ++j) {
            const size_t off = (size_t)(s0 + j) * 1024;
            zb[j] = __half2float(__ldg(zp + off));
            ib[j] = __half2float(__ldg(ip + off));
            fb[j] = __ldg(fp + off);
        }
#pragma unroll
        for (int j = 0; j < 8; ++j) {
            float zv = 1.f - __fdividef(2.f, __expf(2.f * zb[j]) + 1.f);
            float lf = fb[j], li = ib[j];
            if (fminf(fb[j], ib[j]) < -6.f) {
                lf = __logf(__expf(fb[j]) + EPSV);
                li = __logf(__expf(ib[j]) + EPSV);
            }
            F += lf;
            float mn = fmaxf(lf + m, li);
            float ih = __expf(li - mn);
            float fh = __expf(lf + m - mn);
            c = fmaf(fh, c, ih * zv);
            n = fmaf(fh, n, ih);
            m = mn;
        }
    }
    g_cstate[(size_t)k * NCH + ch] = make_float4(F, m, c, n);
}

// ===========================================================================
// Scan phase 2: sequential combine with batch-of-8 register prefetch.
// ===========================================================================
__global__ __launch_bounds__(256) void scan_combine_kernel(float* __restrict__ Out)
{
    const int ch = blockIdx.x * 256 + threadIdx.x;  // 0..4095
    float m = 0.f, c = 0.f, n = 0.f;

#pragma unroll 1
    for (int k0 = 0; k0 < NCHUNK; k0 += 8) {
        float4 buf[8];
#pragma unroll
        for (int j = 0; j < 8; ++j)
            buf[j] = g_cstate[(size_t)(k0 + j) * NCH + ch];
#pragma unroll
        for (int j = 0; j < 8; ++j) {
            g_carry[(size_t)(k0 + j) * NCH + ch] = make_float4(m, c, n, 0.f);
            float4 st = buf[j];  // (F, m_loc, c_loc, n_loc)
            float mo = fmaxf(st.x + m, st.y);
            float ea = __expf(st.x + m - mo);
            float eb = __expf(st.y - mo);
            c = fmaf(ea, c, eb * st.z);
            n = fmaf(ea, n, eb * st.w);
            m = mo;
        }
    }
    Out[8388608 + 4096 + ch]  = c;   // c_f
    Out[8388608 + 8192 + ch]  = n;   // n_f
    Out[8388608 + 12288 + ch] = m;   // m_f
}

// ===========================================================================
// Scan phase 3: replay each chunk from its exact carry-in, batch-of-8 loads.
// ===========================================================================
__global__ __launch_bounds__(256) void scan_emit_kernel(float* __restrict__ Out)
{
    const int ch = blockIdx.x * 256 + threadIdx.x;
    const int k  = blockIdx.y;
    const int b  = ch >> 10;
    const int hd = ch & 1023;
    const size_t rb = (size_t)(b * 2048 + k * CHUNK) * 1024 + hd;
    const __half* zp = g_gz + rb;
    const __half* ip = g_gi + rb;
    const float*  fp = g_gf + rb;
    const __half* op = g_go + rb;
    float* hp = Out + (size_t)b * 2048 * 1024 + (size_t)k * CHUNK * 1024 + hd;

    float4 cr = g_carry[(size_t)k * NCH + ch];
    float m = cr.x, c = cr.y, n = cr.z, hv = 0.f;

#pragma unroll 1
    for (int s0 = 0; s0 < CHUNK; s0 += 8) {
        float zb[8], ib[8], fb[8], ob[8];
#pragma unroll
        for (int j = 0; j < 8; ++j) {
            const size_t off = (size_t)(s0 + j) * 1024;
            zb[j] = __half2float(__ldg(zp + off));
            ib[j] = __half2float(__ldg(ip + off));
            fb[j] = __ldg(fp + off);
            ob[j] = __half2float(__ldg(op + off));
        }
#pragma unroll
        for (int j = 0; j < 8; ++j) {
            float zv = 1.f - __fdividef(2.f, __expf(2.f * zb[j]) + 1.f);
            float ov = __fdividef(1.f, 1.f + __expf(-ob[j]));
            float lf = fb[j], li = ib[j];
            if (fminf(fb[j], ib[j]) < -6.f) {
                lf = __logf(__expf(fb[j]) + EPSV);
                li = __logf(__expf(ib[j]) + EPSV);
            }
            float mn = fmaxf(lf + m, li);
            float ih = __expf(li - mn);
            float fh = __expf(lf + m - mn);
            c = fmaf(fh, c, ih * zv);
            n = fmaf(fh, n, ih);
            m = mn;
            hv = ov * __fdividef(c, n + EPSV);
            hp[(size_t)(s0 + j) * 1024] = hv;
        }
    }

    if (k == NCHUNK - 1) Out[8388608 + ch] = hv;  // h_f
}

// ---------------------------------------------------------------------------
extern "C" void kernel_launch(void* const* d_in, const int* in_sizes, int n_in,
                              void* d_out, int out_size)
{
    const float* X  = (const float*)d_in[0];  // [4, 2048, 4096]
    const float* W  = (const float*)d_in[1];  // [4, 4, 256, 256]
    const float* Bv = (const float*)d_in[2];  // [4, 4, 256]
    float* out = (float*)d_out;

    cudaFuncSetAttribute(gemm_mma_kernel, cudaFuncAttributeMaxDynamicSharedMemorySize,
                         SMEM_GEMM);

    wsplit_kernel<<<1024, 256>>>(W);
    gemm_mma_kernel<<<dim3(256, 4), 512, SMEM_GEMM>>>(X, Bv);
    scan_local_kernel<<<dim3(16, NCHUNK), 256>>>();
    scan_combine_kernel<<<16, 256>>>(out);
    scan_emit_kernel<<<dim3(16, NCHUNK), 256>>>(out);
}